// round 1
// baseline (speedup 1.0000x reference)
#include <cuda_runtime.h>
#include <math.h>

#define B_ 8
#define C_ 512
#define H_ 2048
#define G_ 32
#define CPG (C_/G_)           // 16 channels per group
static const long CH = (long)C_ * H_;   // per-batch plane elements

// Scratch (device globals: allocation-free contract)
__device__ float g_hn[B_*C_*H_];        // groupnorm output, later reused for attn*V result
__device__ float g_q [B_*C_*H_];
__device__ float g_k [B_*C_*H_];
__device__ float g_v [B_*C_*H_];
__device__ float g_s [(long)B_*H_*H_];  // attention scores (128 MB)

// ---------------------------------------------------------------------------
// GroupNorm: one block per (batch, group). 16 ch x 2048 = 32768 floats/group.
// ---------------------------------------------------------------------------
__global__ __launch_bounds__(256) void gn_kernel(const float* __restrict__ x,
                                                 const float* __restrict__ gamma,
                                                 const float* __restrict__ beta,
                                                 float* __restrict__ hn)
{
    const int b = blockIdx.x >> 5;
    const int g = blockIdx.x & 31;
    const long base = ((long)b * C_ + (long)g * CPG) * H_;
    const float4* xp = reinterpret_cast<const float4*>(x + base);
    float4* hp = reinterpret_cast<float4*>(hn + base);
    const int NE4 = CPG * H_ / 4;   // 8192
    const int tid = threadIdx.x;

    float s = 0.f, ss = 0.f;
    for (int i = tid; i < NE4; i += 256) {
        float4 v = xp[i];
        s  += v.x + v.y + v.z + v.w;
        ss += v.x*v.x + v.y*v.y + v.z*v.z + v.w*v.w;
    }
    __shared__ float rs[8], rss[8];
    #pragma unroll
    for (int o = 16; o > 0; o >>= 1) {
        s  += __shfl_down_sync(0xFFFFFFFFu, s,  o);
        ss += __shfl_down_sync(0xFFFFFFFFu, ss, o);
    }
    if ((tid & 31) == 0) { rs[tid >> 5] = s; rss[tid >> 5] = ss; }
    __syncthreads();
    if (tid < 32) {
        s  = (tid < 8) ? rs[tid]  : 0.f;
        ss = (tid < 8) ? rss[tid] : 0.f;
        #pragma unroll
        for (int o = 4; o > 0; o >>= 1) {
            s  += __shfl_down_sync(0xFFFFFFFFu, s,  o);
            ss += __shfl_down_sync(0xFFFFFFFFu, ss, o);
        }
        if (tid == 0) { rs[0] = s; rss[0] = ss; }
    }
    __syncthreads();
    const float mean = rs[0] * (1.f / (CPG * H_));
    const float var  = rss[0] * (1.f / (CPG * H_)) - mean * mean;
    const float inv  = rsqrtf(var + 1e-6f);

    for (int i = tid; i < NE4; i += 256) {
        const int c = g * CPG + (i * 4) / H_;
        const float gm = gamma[c] * inv;
        const float bt = beta[c] - mean * gm;
        float4 v = xp[i];
        float4 o;
        o.x = v.x * gm + bt; o.y = v.y * gm + bt;
        o.z = v.z * gm + bt; o.w = v.w * gm + bt;
        hp[i] = o;
    }
}

// ---------------------------------------------------------------------------
// Row softmax over last dim (2048). One block per row, row held in registers.
// ---------------------------------------------------------------------------
__global__ __launch_bounds__(256) void softmax_kernel(float* __restrict__ w)
{
    float4* row = reinterpret_cast<float4*>(w + (long)blockIdx.x * H_);
    const int tid = threadIdx.x;
    float4 v0 = row[tid];
    float4 v1 = row[tid + 256];

    float m = fmaxf(fmaxf(fmaxf(v0.x, v0.y), fmaxf(v0.z, v0.w)),
                    fmaxf(fmaxf(v1.x, v1.y), fmaxf(v1.z, v1.w)));
    __shared__ float red[8];
    #pragma unroll
    for (int o = 16; o > 0; o >>= 1) m = fmaxf(m, __shfl_xor_sync(0xFFFFFFFFu, m, o));
    if ((tid & 31) == 0) red[tid >> 5] = m;
    __syncthreads();
    if (tid < 32) {
        m = (tid < 8) ? red[tid] : -1e30f;
        #pragma unroll
        for (int o = 4; o > 0; o >>= 1) m = fmaxf(m, __shfl_xor_sync(0xFFFFFFFFu, m, o));
        if (tid == 0) red[0] = m;
    }
    __syncthreads();
    m = red[0];

    v0.x = expf(v0.x - m); v0.y = expf(v0.y - m); v0.z = expf(v0.z - m); v0.w = expf(v0.w - m);
    v1.x = expf(v1.x - m); v1.y = expf(v1.y - m); v1.z = expf(v1.z - m); v1.w = expf(v1.w - m);
    float s = v0.x + v0.y + v0.z + v0.w + v1.x + v1.y + v1.z + v1.w;
    __shared__ float red2[8];
    #pragma unroll
    for (int o = 16; o > 0; o >>= 1) s += __shfl_xor_sync(0xFFFFFFFFu, s, o);
    if ((tid & 31) == 0) red2[tid >> 5] = s;
    __syncthreads();
    if (tid < 32) {
        s = (tid < 8) ? red2[tid] : 0.f;
        #pragma unroll
        for (int o = 4; o > 0; o >>= 1) s += __shfl_xor_sync(0xFFFFFFFFu, s, o);
        if (tid == 0) red2[0] = s;
    }
    __syncthreads();
    const float r = 1.f / red2[0];
    v0.x *= r; v0.y *= r; v0.z *= r; v0.w *= r;
    v1.x *= r; v1.y *= r; v1.z *= r; v1.w *= r;
    row[tid] = v0;
    row[tid + 256] = v1;
}

// ---------------------------------------------------------------------------
// Batched fp32 GEMM: C[m,n] = alpha * sum_k A(m,k)*B(k,n) + bias[m] (+resid)
//   TA=false: A[m*lda + k]   TA=true: A[k*lda + m]
//   TB=false: B[k*ldb + n]   TB=true: B[n*ldb + k]
// 128x128 tile, BK=16, 256 threads, 8x8 per thread. Dims must divide tiles.
// ---------------------------------------------------------------------------
#define BM 128
#define BN 128
#define BK 16
#define TM 8
#define TN 8

template<bool TA, bool TB>
__global__ __launch_bounds__(256) void gemm_kernel(
    const float* __restrict__ Ab, const float* __restrict__ Bb, float* __restrict__ Cb,
    int M, int N, int K, int lda, int ldb, int ldc,
    long sA, long sB, long sC,
    const float* __restrict__ bias, float alpha,
    const float* __restrict__ resid, long sR)
{
    const int bz = blockIdx.z;
    const float* A = Ab + (long)bz * sA;
    const float* B = Bb + (long)bz * sB;
    float* C = Cb + (long)bz * sC;

    __shared__ float As[BK][BM];
    __shared__ float Bs[BK][BN];

    const int tid = threadIdx.x;
    const int m0 = blockIdx.y * BM;
    const int n0 = blockIdx.x * BN;

    float acc[TM][TN] = {};
    const int trl = (tid >> 4) * TM;    // local row base
    const int tcl = (tid & 15) * TN;    // local col base

    for (int k0 = 0; k0 < K; k0 += BK) {
        // ---- load A tile into As[k][m] ----
        if (!TA) {
            const int r  = tid >> 2;
            const int c4 = (tid & 3) * 4;
            #pragma unroll
            for (int i = 0; i < 2; i++) {
                const int m = r + i * 64;
                float4 v = *reinterpret_cast<const float4*>(&A[(long)(m0 + m) * lda + k0 + c4]);
                As[c4 + 0][m] = v.x; As[c4 + 1][m] = v.y;
                As[c4 + 2][m] = v.z; As[c4 + 3][m] = v.w;
            }
        } else {
            const int kk = tid >> 5;
            const int m4 = (tid & 31) * 4;
            #pragma unroll
            for (int i = 0; i < 2; i++) {
                const int k = kk + i * 8;
                float4 v = *reinterpret_cast<const float4*>(&A[(long)(k0 + k) * lda + m0 + m4]);
                *reinterpret_cast<float4*>(&As[k][m4]) = v;
            }
        }
        // ---- load B tile into Bs[k][n] ----
        if (!TB) {
            const int kk = tid >> 5;
            const int n4 = (tid & 31) * 4;
            #pragma unroll
            for (int i = 0; i < 2; i++) {
                const int k = kk + i * 8;
                float4 v = *reinterpret_cast<const float4*>(&B[(long)(k0 + k) * ldb + n0 + n4]);
                *reinterpret_cast<float4*>(&Bs[k][n4]) = v;
            }
        } else {
            const int r  = tid >> 2;
            const int c4 = (tid & 3) * 4;
            #pragma unroll
            for (int i = 0; i < 2; i++) {
                const int n = r + i * 64;
                float4 v = *reinterpret_cast<const float4*>(&B[(long)(n0 + n) * ldb + k0 + c4]);
                Bs[c4 + 0][n] = v.x; Bs[c4 + 1][n] = v.y;
                Bs[c4 + 2][n] = v.z; Bs[c4 + 3][n] = v.w;
            }
        }
        __syncthreads();

        #pragma unroll
        for (int k = 0; k < BK; k++) {
            float ar[TM], br[TN];
            #pragma unroll
            for (int i = 0; i < TM; i++) ar[i] = As[k][trl + i];
            #pragma unroll
            for (int j = 0; j < TN; j++) br[j] = Bs[k][tcl + j];
            #pragma unroll
            for (int i = 0; i < TM; i++)
                #pragma unroll
                for (int j = 0; j < TN; j++)
                    acc[i][j] += ar[i] * br[j];
        }
        __syncthreads();
    }

    // ---- epilogue ----
    const int tr = m0 + trl;
    const int tc = n0 + tcl;
    #pragma unroll
    for (int i = 0; i < TM; i++) {
        const long rowoff = (long)(tr + i) * ldc + tc;
        const float bi = bias ? bias[tr + i] : 0.f;
        #pragma unroll
        for (int j = 0; j < TN; j += 4) {
            float4 v;
            v.x = fmaf(acc[i][j + 0], alpha, bi);
            v.y = fmaf(acc[i][j + 1], alpha, bi);
            v.z = fmaf(acc[i][j + 2], alpha, bi);
            v.w = fmaf(acc[i][j + 3], alpha, bi);
            if (resid) {
                const float4 r = *reinterpret_cast<const float4*>(&resid[bz * sR + rowoff + j]);
                v.x += r.x; v.y += r.y; v.z += r.z; v.w += r.w;
            }
            *reinterpret_cast<float4*>(&C[rowoff + j]) = v;
        }
    }
}

// ---------------------------------------------------------------------------
extern "C" void kernel_launch(void* const* d_in, const int* in_sizes, int n_in,
                              void* d_out, int out_size)
{
    const float* x     = (const float*)d_in[0];
    const float* gamma = (const float*)d_in[1];
    const float* beta  = (const float*)d_in[2];
    const float* wq    = (const float*)d_in[3];
    const float* bq    = (const float*)d_in[4];
    const float* wk    = (const float*)d_in[5];
    const float* bk    = (const float*)d_in[6];
    const float* wv    = (const float*)d_in[7];
    const float* bv    = (const float*)d_in[8];
    const float* wp    = (const float*)d_in[9];
    const float* bp    = (const float*)d_in[10];
    float* out = (float*)d_out;

    float *hn, *q, *k, *v, *s;
    cudaGetSymbolAddress((void**)&hn, g_hn);
    cudaGetSymbolAddress((void**)&q,  g_q);
    cudaGetSymbolAddress((void**)&k,  g_k);
    cudaGetSymbolAddress((void**)&v,  g_v);
    cudaGetSymbolAddress((void**)&s,  g_s);

    const long HH = (long)H_ * H_;
    const float scale = 0.044194173824159216f;   // 1/sqrt(512)

    // 1. GroupNorm
    gn_kernel<<<B_ * G_, 256>>>(x, gamma, beta, hn);

    // 2-4. q/k/v = W(512x512) @ hn_b(512x2048) + bias      (NN, batched over b)
    dim3 gqkv(H_ / BN, C_ / BM, B_);
    gemm_kernel<false, false><<<gqkv, 256>>>(wq, hn, q, C_, H_, C_, C_, H_, H_,
                                             0, CH, CH, bq, 1.f, nullptr, 0);
    gemm_kernel<false, false><<<gqkv, 256>>>(wk, hn, k, C_, H_, C_, C_, H_, H_,
                                             0, CH, CH, bk, 1.f, nullptr, 0);
    gemm_kernel<false, false><<<gqkv, 256>>>(wv, hn, v, C_, H_, C_, C_, H_, H_,
                                             0, CH, CH, bv, 1.f, nullptr, 0);

    // 5. scores s[b,i,j] = scale * sum_c q[b,c,i] k[b,c,j]   (TN)
    dim3 gsc(H_ / BN, H_ / BM, B_);
    gemm_kernel<true, false><<<gsc, 256>>>(q, k, s, H_, H_, C_, H_, H_, H_,
                                           CH, CH, HH, nullptr, scale, nullptr, 0);

    // 6. softmax over j
    softmax_kernel<<<B_ * H_, 256>>>(s);

    // 7. h_[b,c,i] = sum_j v[b,c,j] s[b,i,j]   (NT)  -> reuse g_hn
    dim3 gav(H_ / BN, C_ / BM, B_);
    gemm_kernel<false, true><<<gav, 256>>>(v, s, hn, C_, H_, H_, H_, H_, H_,
                                           CH, HH, CH, nullptr, 1.f, nullptr, 0);

    // 8. out = x + Wp @ h_ + bp   (NN with residual)
    gemm_kernel<false, false><<<gqkv, 256>>>(wp, hn, out, C_, H_, C_, C_, H_, H_,
                                             0, CH, CH, bp, 1.f, x, CH);
}

// round 2
// speedup vs baseline: 4.6499x; 4.6499x over previous
#include <cuda_runtime.h>
#include <cuda_fp16.h>
#include <math.h>
#include <stdint.h>

#define B_ 8
#define C_ 512
#define H_ 2048
#define G_ 32
#define CPG (C_/G_)
static const long CH = (long)C_ * H_;

// Scratch (device globals: allocation-free contract)
__device__ float g_hn[B_*C_*H_];
__device__ float g_q [B_*C_*H_];
__device__ float g_k [B_*C_*H_];
__device__ float g_v [B_*C_*H_];
__device__ float g_s [(long)B_*H_*H_];

// ---------------------------------------------------------------------------
// GroupNorm
// ---------------------------------------------------------------------------
__global__ __launch_bounds__(256) void gn_kernel(const float* __restrict__ x,
                                                 const float* __restrict__ gamma,
                                                 const float* __restrict__ beta,
                                                 float* __restrict__ hn)
{
    const int b = blockIdx.x >> 5;
    const int g = blockIdx.x & 31;
    const long base = ((long)b * C_ + (long)g * CPG) * H_;
    const float4* xp = reinterpret_cast<const float4*>(x + base);
    float4* hp = reinterpret_cast<float4*>(hn + base);
    const int NE4 = CPG * H_ / 4;
    const int tid = threadIdx.x;

    float s = 0.f, ss = 0.f;
    for (int i = tid; i < NE4; i += 256) {
        float4 v = xp[i];
        s  += v.x + v.y + v.z + v.w;
        ss += v.x*v.x + v.y*v.y + v.z*v.z + v.w*v.w;
    }
    __shared__ float rs[8], rss[8];
    #pragma unroll
    for (int o = 16; o > 0; o >>= 1) {
        s  += __shfl_down_sync(0xFFFFFFFFu, s,  o);
        ss += __shfl_down_sync(0xFFFFFFFFu, ss, o);
    }
    if ((tid & 31) == 0) { rs[tid >> 5] = s; rss[tid >> 5] = ss; }
    __syncthreads();
    if (tid < 32) {
        s  = (tid < 8) ? rs[tid]  : 0.f;
        ss = (tid < 8) ? rss[tid] : 0.f;
        #pragma unroll
        for (int o = 4; o > 0; o >>= 1) {
            s  += __shfl_down_sync(0xFFFFFFFFu, s,  o);
            ss += __shfl_down_sync(0xFFFFFFFFu, ss, o);
        }
        if (tid == 0) { rs[0] = s; rss[0] = ss; }
    }
    __syncthreads();
    const float mean = rs[0] * (1.f / (CPG * H_));
    const float var  = rss[0] * (1.f / (CPG * H_)) - mean * mean;
    const float inv  = rsqrtf(var + 1e-6f);

    for (int i = tid; i < NE4; i += 256) {
        const int c = g * CPG + (i * 4) / H_;
        const float gm = gamma[c] * inv;
        const float bt = beta[c] - mean * gm;
        float4 v = xp[i];
        float4 o;
        o.x = v.x * gm + bt; o.y = v.y * gm + bt;
        o.z = v.z * gm + bt; o.w = v.w * gm + bt;
        hp[i] = o;
    }
}

// ---------------------------------------------------------------------------
// Row softmax over last dim (2048)
// ---------------------------------------------------------------------------
__global__ __launch_bounds__(256) void softmax_kernel(float* __restrict__ w)
{
    float4* row = reinterpret_cast<float4*>(w + (long)blockIdx.x * H_);
    const int tid = threadIdx.x;
    float4 v0 = row[tid];
    float4 v1 = row[tid + 256];

    float m = fmaxf(fmaxf(fmaxf(v0.x, v0.y), fmaxf(v0.z, v0.w)),
                    fmaxf(fmaxf(v1.x, v1.y), fmaxf(v1.z, v1.w)));
    __shared__ float red[8];
    #pragma unroll
    for (int o = 16; o > 0; o >>= 1) m = fmaxf(m, __shfl_xor_sync(0xFFFFFFFFu, m, o));
    if ((tid & 31) == 0) red[tid >> 5] = m;
    __syncthreads();
    if (tid < 32) {
        m = (tid < 8) ? red[tid] : -1e30f;
        #pragma unroll
        for (int o = 4; o > 0; o >>= 1) m = fmaxf(m, __shfl_xor_sync(0xFFFFFFFFu, m, o));
        if (tid == 0) red[0] = m;
    }
    __syncthreads();
    m = red[0];

    v0.x = expf(v0.x - m); v0.y = expf(v0.y - m); v0.z = expf(v0.z - m); v0.w = expf(v0.w - m);
    v1.x = expf(v1.x - m); v1.y = expf(v1.y - m); v1.z = expf(v1.z - m); v1.w = expf(v1.w - m);
    float s = v0.x + v0.y + v0.z + v0.w + v1.x + v1.y + v1.z + v1.w;
    __shared__ float red2[8];
    #pragma unroll
    for (int o = 16; o > 0; o >>= 1) s += __shfl_xor_sync(0xFFFFFFFFu, s, o);
    if ((tid & 31) == 0) red2[tid >> 5] = s;
    __syncthreads();
    if (tid < 32) {
        s = (tid < 8) ? red2[tid] : 0.f;
        #pragma unroll
        for (int o = 4; o > 0; o >>= 1) s += __shfl_xor_sync(0xFFFFFFFFu, s, o);
        if (tid == 0) red2[0] = s;
    }
    __syncthreads();
    const float r = 1.f / red2[0];
    v0.x *= r; v0.y *= r; v0.z *= r; v0.w *= r;
    v1.x *= r; v1.y *= r; v1.z *= r; v1.w *= r;
    row[tid] = v0;
    row[tid + 256] = v1;
}

// ---------------------------------------------------------------------------
// Tensor-core fp16 GEMM (fp32 in/out, fp32 accumulate)
//   C[m,n] = alpha * sum_k A(m,k)*B(k,n) + bias[m] (+resid)
//   TA=false: A gmem [m][k]   TA=true: A gmem [k][m]
//   TB=false: B gmem [k][n]   TB=true: B gmem [n][k]
// Tiles: BM=BN=128, BK=32. 256 threads = 8 warps (2x4), 64x32 per warp.
// ---------------------------------------------------------------------------
#define BM 128
#define BN 128
#define BK 32
#define PA 40    // pitch (halves) for m/n-major smem rows (32 data + 8 pad), 80B
#define PK 136   // pitch (halves) for k-major smem rows (128 data + 8 pad), 272B

__device__ __forceinline__ uint32_t smem_u32(const void* p) {
    return (uint32_t)__cvta_generic_to_shared(p);
}
__device__ __forceinline__ void ldsm4(uint32_t* r, uint32_t a) {
    asm volatile("ldmatrix.sync.aligned.m8n8.x4.shared.b16 {%0,%1,%2,%3}, [%4];"
                 : "=r"(r[0]), "=r"(r[1]), "=r"(r[2]), "=r"(r[3]) : "r"(a));
}
__device__ __forceinline__ void ldsm4t(uint32_t* r, uint32_t a) {
    asm volatile("ldmatrix.sync.aligned.m8n8.x4.trans.shared.b16 {%0,%1,%2,%3}, [%4];"
                 : "=r"(r[0]), "=r"(r[1]), "=r"(r[2]), "=r"(r[3]) : "r"(a));
}
__device__ __forceinline__ void ldsm2(uint32_t* r, uint32_t a) {
    asm volatile("ldmatrix.sync.aligned.m8n8.x2.shared.b16 {%0,%1}, [%2];"
                 : "=r"(r[0]), "=r"(r[1]) : "r"(a));
}
__device__ __forceinline__ void ldsm2t(uint32_t* r, uint32_t a) {
    asm volatile("ldmatrix.sync.aligned.m8n8.x2.trans.shared.b16 {%0,%1}, [%2];"
                 : "=r"(r[0]), "=r"(r[1]) : "r"(a));
}
__device__ __forceinline__ void mma16816(float* c, const uint32_t* a, const uint32_t* b) {
    asm volatile("mma.sync.aligned.m16n8k16.row.col.f32.f16.f16.f32 "
                 "{%0,%1,%2,%3}, {%4,%5,%6,%7}, {%8,%9}, {%0,%1,%2,%3};"
                 : "+f"(c[0]), "+f"(c[1]), "+f"(c[2]), "+f"(c[3])
                 : "r"(a[0]), "r"(a[1]), "r"(a[2]), "r"(a[3]), "r"(b[0]), "r"(b[1]));
}
__device__ __forceinline__ void st_h4(__half* dst, float4 v) {
    __half2 lo = __floats2half2_rn(v.x, v.y);
    __half2 hi = __floats2half2_rn(v.z, v.w);
    uint2 u;
    u.x = *reinterpret_cast<uint32_t*>(&lo);
    u.y = *reinterpret_cast<uint32_t*>(&hi);
    *reinterpret_cast<uint2*>(dst) = u;
}

template<bool TA, bool TB>
__global__ __launch_bounds__(256, 2) void hgemm_kernel(
    const float* __restrict__ Ab, const float* __restrict__ Bb, float* __restrict__ Cb,
    int K, int lda, int ldb, int ldc,
    long sA, long sB, long sC,
    const float* __restrict__ bias, float alpha,
    const float* __restrict__ resid, long sR)
{
    __shared__ alignas(16) __half Asm[TA ? (BK*PK) : (BM*PA)];
    __shared__ alignas(16) __half Bsm[TB ? (BN*PA) : (BK*PK)];

    const int tid = threadIdx.x;
    const int bz = blockIdx.z;
    const float* A = Ab + (long)bz * sA;
    const float* B = Bb + (long)bz * sB;
    float* C = Cb + (long)bz * sC;
    const int m0 = blockIdx.y * BM;
    const int n0 = blockIdx.x * BN;

    const int wid = tid >> 5, lane = tid & 31;
    const int wm = (wid & 1) * 64;
    const int wn = (wid >> 1) * 32;

    float acc[4][4][4] = {};

    for (int k0 = 0; k0 < K; k0 += BK) {
        // ---- stage A ----
        if (!TA) {
            const int mr = tid >> 3;
            const int kq = (tid & 7) * 4;
            #pragma unroll
            for (int i = 0; i < 4; i++) {
                const int m = mr + i * 32;
                float4 v = *reinterpret_cast<const float4*>(&A[(long)(m0 + m) * lda + k0 + kq]);
                st_h4(&Asm[m * PA + kq], v);
            }
        } else {
            const int kr = tid >> 5;
            const int m4 = (tid & 31) * 4;
            #pragma unroll
            for (int i = 0; i < 4; i++) {
                const int k = kr + i * 8;
                float4 v = *reinterpret_cast<const float4*>(&A[(long)(k0 + k) * lda + m0 + m4]);
                st_h4(&Asm[k * PK + m4], v);
            }
        }
        // ---- stage B ----
        if (!TB) {
            const int kr = tid >> 5;
            const int n4 = (tid & 31) * 4;
            #pragma unroll
            for (int i = 0; i < 4; i++) {
                const int k = kr + i * 8;
                float4 v = *reinterpret_cast<const float4*>(&B[(long)(k0 + k) * ldb + n0 + n4]);
                st_h4(&Bsm[k * PK + n4], v);
            }
        } else {
            const int nr = tid >> 3;
            const int kq = (tid & 7) * 4;
            #pragma unroll
            for (int i = 0; i < 4; i++) {
                const int n = nr + i * 32;
                float4 v = *reinterpret_cast<const float4*>(&B[(long)(n0 + n) * ldb + k0 + kq]);
                st_h4(&Bsm[n * PA + kq], v);
            }
        }
        __syncthreads();

        #pragma unroll
        for (int ks = 0; ks < BK; ks += 16) {
            uint32_t a[4][4], b[4][2];
            #pragma unroll
            for (int mt = 0; mt < 4; mt++) {
                if (!TA) {
                    const int row = wm + mt * 16 + (lane & 15);
                    ldsm4(a[mt], smem_u32(&Asm[row * PA + ks + (lane >> 4) * 8]));
                } else {
                    const int kk = ks + (lane >> 4) * 8 + (lane & 7);
                    const int mm = wm + mt * 16 + ((lane >> 3) & 1) * 8;
                    ldsm4t(a[mt], smem_u32(&Asm[kk * PK + mm]));
                }
            }
            #pragma unroll
            for (int nt = 0; nt < 4; nt++) {
                const int l = lane & 15;
                if (!TB) {
                    const int kk = ks + l;
                    ldsm2t(b[nt], smem_u32(&Bsm[kk * PK + wn + nt * 8]));
                } else {
                    const int nn = wn + nt * 8 + (l & 7);
                    ldsm2(b[nt], smem_u32(&Bsm[nn * PA + ks + (l >> 3) * 8]));
                }
            }
            #pragma unroll
            for (int mt = 0; mt < 4; mt++)
                #pragma unroll
                for (int nt = 0; nt < 4; nt++)
                    mma16816(acc[mt][nt], a[mt], b[nt]);
        }
        __syncthreads();
    }

    // ---- epilogue ----
    const int r0 = m0 + wm + (lane >> 2);
    const int c0 = n0 + wn + (lane & 3) * 2;
    #pragma unroll
    for (int mt = 0; mt < 4; mt++) {
        #pragma unroll
        for (int nt = 0; nt < 4; nt++) {
            const float* a4 = acc[mt][nt];
            const int r = r0 + mt * 16;
            const int c = c0 + nt * 8;
            #pragma unroll
            for (int h = 0; h < 2; h++) {
                const int rr = r + h * 8;
                const float bi = bias ? bias[rr] : 0.f;
                float2 v;
                v.x = fmaf(a4[h * 2 + 0], alpha, bi);
                v.y = fmaf(a4[h * 2 + 1], alpha, bi);
                const long off = (long)rr * ldc + c;
                if (resid) {
                    const float2 rv = *reinterpret_cast<const float2*>(&resid[(long)bz * sR + off]);
                    v.x += rv.x; v.y += rv.y;
                }
                *reinterpret_cast<float2*>(&C[off]) = v;
            }
        }
    }
}

// ---------------------------------------------------------------------------
extern "C" void kernel_launch(void* const* d_in, const int* in_sizes, int n_in,
                              void* d_out, int out_size)
{
    const float* x     = (const float*)d_in[0];
    const float* gamma = (const float*)d_in[1];
    const float* beta  = (const float*)d_in[2];
    const float* wq    = (const float*)d_in[3];
    const float* bq    = (const float*)d_in[4];
    const float* wk    = (const float*)d_in[5];
    const float* bk    = (const float*)d_in[6];
    const float* wv    = (const float*)d_in[7];
    const float* bv    = (const float*)d_in[8];
    const float* wp    = (const float*)d_in[9];
    const float* bp    = (const float*)d_in[10];
    float* out = (float*)d_out;

    float *hn, *q, *k, *v, *s;
    cudaGetSymbolAddress((void**)&hn, g_hn);
    cudaGetSymbolAddress((void**)&q,  g_q);
    cudaGetSymbolAddress((void**)&k,  g_k);
    cudaGetSymbolAddress((void**)&v,  g_v);
    cudaGetSymbolAddress((void**)&s,  g_s);

    const long HH = (long)H_ * H_;
    const float scale = 0.044194173824159216f;   // 1/sqrt(512)

    // 1. GroupNorm
    gn_kernel<<<B_ * G_, 256>>>(x, gamma, beta, hn);

    // 2-4. q/k/v = W @ hn_b + bias   (A=[m,k], B=[k,n])
    dim3 gqkv(H_ / BN, C_ / BM, B_);
    hgemm_kernel<false, false><<<gqkv, 256>>>(wq, hn, q, C_, C_, H_, H_,
                                              0, CH, CH, bq, 1.f, nullptr, 0);
    hgemm_kernel<false, false><<<gqkv, 256>>>(wk, hn, k, C_, C_, H_, H_,
                                              0, CH, CH, bk, 1.f, nullptr, 0);
    hgemm_kernel<false, false><<<gqkv, 256>>>(wv, hn, v, C_, C_, H_, H_,
                                              0, CH, CH, bv, 1.f, nullptr, 0);

    // 5. scores s[b,i,j] = scale * sum_c q[b,c,i] k[b,c,j]   (A=[k,m], B=[k,n])
    dim3 gsc(H_ / BN, H_ / BM, B_);
    hgemm_kernel<true, false><<<gsc, 256>>>(q, k, s, C_, H_, H_, H_,
                                            CH, CH, HH, nullptr, scale, nullptr, 0);

    // 6. softmax over j
    softmax_kernel<<<B_ * H_, 256>>>(s);

    // 7. h_[b,c,i] = sum_j v[b,c,j] p[i,j]   (A=[m,k], B=[n,k])
    dim3 gav(H_ / BN, C_ / BM, B_);
    hgemm_kernel<false, true><<<gav, 256>>>(v, s, hn, H_, H_, H_, H_,
                                            CH, HH, CH, nullptr, 1.f, nullptr, 0);

    // 8. out = x + Wp @ h_ + bp
    hgemm_kernel<false, false><<<gqkv, 256>>>(wp, hn, out, C_, C_, H_, H_,
                                              0, CH, CH, bp, 1.f, x, CH);
}

// round 4
// speedup vs baseline: 6.1532x; 1.3233x over previous
#include <cuda_runtime.h>
#include <cuda_fp16.h>
#include <math.h>
#include <stdint.h>

#define B_ 8
#define C_ 512
#define H_ 2048
#define G_ 32
#define CPG 16
static const long CH = (long)C_ * H_;

// Scratch (device globals: allocation-free contract). All fp16 intermediates.
__device__ __half g_hn[B_*C_*H_];        // GN output; later reused for attn*V output
__device__ __half g_q [B_*C_*H_];
__device__ __half g_k [B_*C_*H_];
__device__ __half g_v [B_*C_*H_];
__device__ __half g_s [(long)B_*H_*H_]; // attention scores/probs (64 MB fp16)
__device__ __half g_w [4*C_*C_];        // fp16 weights: wq,wk,wv,wp

__device__ __forceinline__ uint32_t smem_u32(const void* p) {
    return (uint32_t)__cvta_generic_to_shared(p);
}
__device__ __forceinline__ void st_h4(__half* dst, float4 v) {
    __half2 lo = __floats2half2_rn(v.x, v.y);
    __half2 hi = __floats2half2_rn(v.z, v.w);
    uint2 u;
    u.x = *reinterpret_cast<uint32_t*>(&lo);
    u.y = *reinterpret_cast<uint32_t*>(&hi);
    *reinterpret_cast<uint2*>(dst) = u;
}

// ---------------------------------------------------------------------------
// Weight fp32 -> fp16 conversion (4 x 512 x 512)
// ---------------------------------------------------------------------------
__global__ __launch_bounds__(256) void w2h_kernel(const float* __restrict__ wq,
                                                  const float* __restrict__ wk,
                                                  const float* __restrict__ wv,
                                                  const float* __restrict__ wp,
                                                  __half* __restrict__ dst)
{
    const int gid = blockIdx.x * 256 + threadIdx.x;   // one float4 each
    const int mat = gid >> 16;                        // C*C/4 = 65536
    const int off = (gid & 65535) * 4;
    const float* src = (mat == 0) ? wq : (mat == 1) ? wk : (mat == 2) ? wv : wp;
    float4 v = *reinterpret_cast<const float4*>(src + off);
    st_h4(&dst[(long)mat * C_ * C_ + off], v);
}

// ---------------------------------------------------------------------------
// GroupNorm -> fp16 output
// ---------------------------------------------------------------------------
__global__ __launch_bounds__(256) void gn_kernel(const float* __restrict__ x,
                                                 const float* __restrict__ gamma,
                                                 const float* __restrict__ beta,
                                                 __half* __restrict__ hn)
{
    const int b = blockIdx.x >> 5;
    const int g = blockIdx.x & 31;
    const long base = ((long)b * C_ + (long)g * CPG) * H_;
    const float4* xp = reinterpret_cast<const float4*>(x + base);
    const int NE4 = CPG * H_ / 4;
    const int tid = threadIdx.x;

    float s = 0.f, ss = 0.f;
    for (int i = tid; i < NE4; i += 256) {
        float4 v = xp[i];
        s  += v.x + v.y + v.z + v.w;
        ss += v.x*v.x + v.y*v.y + v.z*v.z + v.w*v.w;
    }
    __shared__ float rs[8], rss[8];
    #pragma unroll
    for (int o = 16; o > 0; o >>= 1) {
        s  += __shfl_down_sync(0xFFFFFFFFu, s,  o);
        ss += __shfl_down_sync(0xFFFFFFFFu, ss, o);
    }
    if ((tid & 31) == 0) { rs[tid >> 5] = s; rss[tid >> 5] = ss; }
    __syncthreads();
    if (tid < 32) {
        s  = (tid < 8) ? rs[tid]  : 0.f;
        ss = (tid < 8) ? rss[tid] : 0.f;
        #pragma unroll
        for (int o = 4; o > 0; o >>= 1) {
            s  += __shfl_down_sync(0xFFFFFFFFu, s,  o);
            ss += __shfl_down_sync(0xFFFFFFFFu, ss, o);
        }
        if (tid == 0) { rs[0] = s; rss[0] = ss; }
    }
    __syncthreads();
    const float mean = rs[0] * (1.f / (CPG * H_));
    const float var  = rss[0] * (1.f / (CPG * H_)) - mean * mean;
    const float inv  = rsqrtf(var + 1e-6f);

    for (int i = tid; i < NE4; i += 256) {
        const int c = g * CPG + (i * 4) / H_;
        const float gm = gamma[c] * inv;
        const float bt = beta[c] - mean * gm;
        float4 v = xp[i];
        float4 o;
        o.x = v.x * gm + bt; o.y = v.y * gm + bt;
        o.z = v.z * gm + bt; o.w = v.w * gm + bt;
        st_h4(&hn[base + (long)i * 4], o);
    }
}

// ---------------------------------------------------------------------------
// Row softmax over last dim (2048), fp16 in/out, fp32 math.
// 256 threads, 8 halves per thread.
// ---------------------------------------------------------------------------
__global__ __launch_bounds__(256) void softmax_kernel(__half* __restrict__ w)
{
    uint4* row = reinterpret_cast<uint4*>(w + (long)blockIdx.x * H_);
    const int tid = threadIdx.x;
    uint4 u = row[tid];
    __half2* hp = reinterpret_cast<__half2*>(&u);
    float f[8];
    #pragma unroll
    for (int i = 0; i < 4; i++) {
        float2 p = __half22float2(hp[i]);
        f[2*i] = p.x; f[2*i+1] = p.y;
    }

    float m = f[0];
    #pragma unroll
    for (int i = 1; i < 8; i++) m = fmaxf(m, f[i]);
    __shared__ float red[8];
    #pragma unroll
    for (int o = 16; o > 0; o >>= 1) m = fmaxf(m, __shfl_xor_sync(0xFFFFFFFFu, m, o));
    if ((tid & 31) == 0) red[tid >> 5] = m;
    __syncthreads();
    if (tid < 32) {
        m = (tid < 8) ? red[tid] : -1e30f;
        #pragma unroll
        for (int o = 4; o > 0; o >>= 1) m = fmaxf(m, __shfl_xor_sync(0xFFFFFFFFu, m, o));
        if (tid == 0) red[0] = m;
    }
    __syncthreads();
    m = red[0];

    float s = 0.f;
    #pragma unroll
    for (int i = 0; i < 8; i++) { f[i] = expf(f[i] - m); s += f[i]; }
    __shared__ float red2[8];
    #pragma unroll
    for (int o = 16; o > 0; o >>= 1) s += __shfl_xor_sync(0xFFFFFFFFu, s, o);
    if ((tid & 31) == 0) red2[tid >> 5] = s;
    __syncthreads();
    if (tid < 32) {
        s = (tid < 8) ? red2[tid] : 0.f;
        #pragma unroll
        for (int o = 4; o > 0; o >>= 1) s += __shfl_xor_sync(0xFFFFFFFFu, s, o);
        if (tid == 0) red2[0] = s;
    }
    __syncthreads();
    const float r = 1.f / red2[0];
    #pragma unroll
    for (int i = 0; i < 4; i++)
        hp[i] = __floats2half2_rn(f[2*i] * r, f[2*i+1] * r);
    row[tid] = u;
}

// ---------------------------------------------------------------------------
// Tensor-core fp16 GEMM, cp.async double-buffered.
//   C[m,n] = alpha * sum_k A(m,k)*B(k,n) + bias[m] (+resid fp32)
//   TA=false: A gmem [m][k]   TA=true: A gmem [k][m]
//   TB=false: B gmem [k][n]   TB=true: B gmem [n][k]
// All A/B operands fp16. OutT = __half or float.
// Tiles: BM=BN=128, BK=32. 8 warps (2x4), 64x32 per warp.
// ---------------------------------------------------------------------------
#define BM 128
#define BN 128
#define BK 32
#define PA 40    // pitch (halves) m/n-major rows: 80B  (16B-aligned rows)
#define PK 136   // pitch (halves) k-major rows:   272B (16B-aligned rows)

__device__ __forceinline__ void cp16(void* s, const void* g) {
    asm volatile("cp.async.cg.shared.global [%0], [%1], 16;"
                 :: "r"(smem_u32(s)), "l"(g));
}
__device__ __forceinline__ void cp_commit() { asm volatile("cp.async.commit_group;"); }
__device__ __forceinline__ void cp_wait1() { asm volatile("cp.async.wait_group 1;"); }
__device__ __forceinline__ void cp_wait0() { asm volatile("cp.async.wait_group 0;"); }

__device__ __forceinline__ void ldsm4(uint32_t* r, uint32_t a) {
    asm volatile("ldmatrix.sync.aligned.m8n8.x4.shared.b16 {%0,%1,%2,%3}, [%4];"
                 : "=r"(r[0]), "=r"(r[1]), "=r"(r[2]), "=r"(r[3]) : "r"(a));
}
__device__ __forceinline__ void ldsm4t(uint32_t* r, uint32_t a) {
    asm volatile("ldmatrix.sync.aligned.m8n8.x4.trans.shared.b16 {%0,%1,%2,%3}, [%4];"
                 : "=r"(r[0]), "=r"(r[1]), "=r"(r[2]), "=r"(r[3]) : "r"(a));
}
__device__ __forceinline__ void ldsm2(uint32_t* r, uint32_t a) {
    asm volatile("ldmatrix.sync.aligned.m8n8.x2.shared.b16 {%0,%1}, [%2];"
                 : "=r"(r[0]), "=r"(r[1]) : "r"(a));
}
__device__ __forceinline__ void ldsm2t(uint32_t* r, uint32_t a) {
    asm volatile("ldmatrix.sync.aligned.m8n8.x2.trans.shared.b16 {%0,%1}, [%2];"
                 : "=r"(r[0]), "=r"(r[1]) : "r"(a));
}
__device__ __forceinline__ void mma16816(float* c, const uint32_t* a, const uint32_t* b) {
    asm volatile("mma.sync.aligned.m16n8k16.row.col.f32.f16.f16.f32 "
                 "{%0,%1,%2,%3}, {%4,%5,%6,%7}, {%8,%9}, {%0,%1,%2,%3};"
                 : "+f"(c[0]), "+f"(c[1]), "+f"(c[2]), "+f"(c[3])
                 : "r"(a[0]), "r"(a[1]), "r"(a[2]), "r"(a[3]), "r"(b[0]), "r"(b[1]));
}
__device__ __forceinline__ void store2(float* p, float x, float y) {
    *reinterpret_cast<float2*>(p) = make_float2(x, y);
}
__device__ __forceinline__ void store2(__half* p, float x, float y) {
    *reinterpret_cast<__half2*>(p) = __floats2half2_rn(x, y);
}

template<bool TA, bool TB, typename OutT>
__global__ __launch_bounds__(256, 2) void hgemm_kernel(
    const __half* __restrict__ Ab, const __half* __restrict__ Bb, OutT* __restrict__ Cb,
    int K, int lda, int ldb, int ldc,
    long sA, long sB, long sC,
    const float* __restrict__ bias, float alpha,
    const float* __restrict__ resid, long sR)
{
    __shared__ alignas(16) __half Asm[2][TA ? (BK*PK) : (BM*PA)];
    __shared__ alignas(16) __half Bsm[2][TB ? (BN*PA) : (BK*PK)];

    const int tid = threadIdx.x;
    const int bz = blockIdx.z;
    const __half* A = Ab + (long)bz * sA;
    const __half* B = Bb + (long)bz * sB;
    OutT* C = Cb + (long)bz * sC;
    const int m0 = blockIdx.y * BM;
    const int n0 = blockIdx.x * BN;

    const int wid = tid >> 5, lane = tid & 31;
    const int wm = (wid & 1) * 64;
    const int wn = (wid >> 1) * 32;

    float acc[4][4][4] = {};

    // stage one k-tile (A: 512 16B chunks, B: 512 16B chunks; 2+2 per thread)
    auto stage = [&](int k0, int buf) {
        #pragma unroll
        for (int i = 0; i < 2; i++) {
            const int c = tid + i * 256;
            if (!TA) {
                const int row = c >> 2, kc = c & 3;
                cp16(&Asm[buf][row * PA + kc * 8],
                     &A[(long)(m0 + row) * lda + k0 + kc * 8]);
            } else {
                const int row = c >> 4, mc = c & 15;
                cp16(&Asm[buf][row * PK + mc * 8],
                     &A[(long)(k0 + row) * lda + m0 + mc * 8]);
            }
        }
        #pragma unroll
        for (int i = 0; i < 2; i++) {
            const int c = tid + i * 256;
            if (!TB) {
                const int row = c >> 4, nc = c & 15;
                cp16(&Bsm[buf][row * PK + nc * 8],
                     &B[(long)(k0 + row) * ldb + n0 + nc * 8]);
            } else {
                const int row = c >> 2, kc = c & 3;
                cp16(&Bsm[buf][row * PA + kc * 8],
                     &B[(long)(n0 + row) * ldb + k0 + kc * 8]);
            }
        }
        cp_commit();
    };

    stage(0, 0);
    const int T = K / BK;
    int buf = 0;
    for (int t = 0; t < T; t++) {
        if (t + 1 < T) { stage((t + 1) * BK, buf ^ 1); cp_wait1(); }
        else           { cp_wait0(); }
        __syncthreads();

        #pragma unroll
        for (int ks = 0; ks < BK; ks += 16) {
            uint32_t a[4][4], b[4][2];
            #pragma unroll
            for (int mt = 0; mt < 4; mt++) {
                if (!TA) {
                    const int row = wm + mt * 16 + (lane & 15);
                    ldsm4(a[mt], smem_u32(&Asm[buf][row * PA + ks + (lane >> 4) * 8]));
                } else {
                    const int kk = ks + (lane >> 4) * 8 + (lane & 7);
                    const int mm = wm + mt * 16 + ((lane >> 3) & 1) * 8;
                    ldsm4t(a[mt], smem_u32(&Asm[buf][kk * PK + mm]));
                }
            }
            #pragma unroll
            for (int nt = 0; nt < 4; nt++) {
                const int l = lane & 15;
                if (!TB) {
                    const int kk = ks + l;
                    ldsm2t(b[nt], smem_u32(&Bsm[buf][kk * PK + wn + nt * 8]));
                } else {
                    const int nn = wn + nt * 8 + (l & 7);
                    ldsm2(b[nt], smem_u32(&Bsm[buf][nn * PA + ks + (l >> 3) * 8]));
                }
            }
            #pragma unroll
            for (int mt = 0; mt < 4; mt++)
                #pragma unroll
                for (int nt = 0; nt < 4; nt++)
                    mma16816(acc[mt][nt], a[mt], b[nt]);
        }
        buf ^= 1;
        __syncthreads();
    }

    // ---- epilogue ----
    const int r0 = m0 + wm + (lane >> 2);
    const int c0 = n0 + wn + (lane & 3) * 2;
    #pragma unroll
    for (int mt = 0; mt < 4; mt++) {
        #pragma unroll
        for (int nt = 0; nt < 4; nt++) {
            const float* a4 = acc[mt][nt];
            const int r = r0 + mt * 16;
            const int c = c0 + nt * 8;
            #pragma unroll
            for (int h = 0; h < 2; h++) {
                const int rr = r + h * 8;
                const float bi = bias ? bias[rr] : 0.f;
                float vx = fmaf(a4[h * 2 + 0], alpha, bi);
                float vy = fmaf(a4[h * 2 + 1], alpha, bi);
                const long off = (long)rr * ldc + c;
                if (resid) {
                    const float2 rv = *reinterpret_cast<const float2*>(&resid[(long)bz * sR + off]);
                    vx += rv.x; vy += rv.y;
                }
                store2(&C[off], vx, vy);
            }
        }
    }
}

// ---------------------------------------------------------------------------
extern "C" void kernel_launch(void* const* d_in, const int* in_sizes, int n_in,
                              void* d_out, int out_size)
{
    const float* x     = (const float*)d_in[0];
    const float* gamma = (const float*)d_in[1];
    const float* beta  = (const float*)d_in[2];
    const float* wq    = (const float*)d_in[3];
    const float* bq    = (const float*)d_in[4];
    const float* wk    = (const float*)d_in[5];
    const float* bk    = (const float*)d_in[6];
    const float* wv    = (const float*)d_in[7];
    const float* bv    = (const float*)d_in[8];
    const float* wp    = (const float*)d_in[9];
    const float* bp    = (const float*)d_in[10];
    float* out = (float*)d_out;

    __half *hn, *q, *k, *v, *s, *w;
    cudaGetSymbolAddress((void**)&hn, g_hn);
    cudaGetSymbolAddress((void**)&q,  g_q);
    cudaGetSymbolAddress((void**)&k,  g_k);
    cudaGetSymbolAddress((void**)&v,  g_v);
    cudaGetSymbolAddress((void**)&s,  g_s);
    cudaGetSymbolAddress((void**)&w,  g_w);

    const long HH = (long)H_ * H_;
    const long CC = (long)C_ * C_;
    const float scale = 0.044194173824159216f;   // 1/sqrt(512)

    // 0. weights -> fp16 ; 1. GroupNorm -> fp16
    w2h_kernel<<<1024, 256>>>(wq, wk, wv, wp, w);
    gn_kernel<<<B_ * G_, 256>>>(x, gamma, beta, hn);

    // 2-4. q/k/v = W @ hn_b + bias   (A=[m,k], B=[k,n])
    dim3 gqkv(H_ / BN, C_ / BM, B_);
    hgemm_kernel<false, false, __half><<<gqkv, 256>>>(w + 0*CC, hn, q, C_, C_, H_, H_,
                                                      0, CH, CH, bq, 1.f, nullptr, 0);
    hgemm_kernel<false, false, __half><<<gqkv, 256>>>(w + 1*CC, hn, k, C_, C_, H_, H_,
                                                      0, CH, CH, bk, 1.f, nullptr, 0);
    hgemm_kernel<false, false, __half><<<gqkv, 256>>>(w + 2*CC, hn, v, C_, C_, H_, H_,
                                                      0, CH, CH, bv, 1.f, nullptr, 0);

    // 5. scores s[b,i,j] = scale * sum_c q[b,c,i] k[b,c,j]   (A=[k,m], B=[k,n])
    dim3 gsc(H_ / BN, H_ / BM, B_);
    hgemm_kernel<true, false, __half><<<gsc, 256>>>(q, k, s, C_, H_, H_, H_,
                                                    CH, CH, HH, nullptr, scale, nullptr, 0);

    // 6. softmax over j
    softmax_kernel<<<B_ * H_, 256>>>(s);

    // 7. h_[b,c,i] = sum_j v[b,c,j] p[i,j]   (A=[m,k], B=[n,k]) -> reuse g_hn
    dim3 gav(H_ / BN, C_ / BM, B_);
    hgemm_kernel<false, true, __half><<<gav, 256>>>(v, s, hn, H_, H_, H_, H_,
                                                    CH, HH, CH, nullptr, 1.f, nullptr, 0);

    // 8. out = x + Wp @ h_ + bp  (fp32 out, residual)
    hgemm_kernel<false, false, float><<<gqkv, 256>>>(w + 3*CC, hn, out, C_, C_, H_, H_,
                                                     0, CH, CH, bp, 1.f, x, CH);
}

// round 6
// speedup vs baseline: 6.2043x; 1.0083x over previous
#include <cuda_runtime.h>
#include <cuda_fp16.h>
#include <math.h>
#include <stdint.h>

#define B_ 8
#define C_ 512
#define H_ 2048
#define G_ 32
#define CPG 16
static const long CH = (long)C_ * H_;

// Scratch (device globals: allocation-free contract). All fp16 intermediates.
__device__ __half g_hn[B_*C_*H_];        // GN output; later reused for attn*V output
__device__ __half g_q [B_*C_*H_];
__device__ __half g_k [B_*C_*H_];
__device__ __half g_v [B_*C_*H_];
__device__ __half g_s [(long)B_*H_*H_]; // attention scores/probs (64 MB fp16)
__device__ __half g_w [4*C_*C_];        // fp16 weights: wq,wk,wv,wp

__device__ __forceinline__ uint32_t smem_u32(const void* p) {
    return (uint32_t)__cvta_generic_to_shared(p);
}
__device__ __forceinline__ void st_h4(__half* dst, float4 v) {
    __half2 lo = __floats2half2_rn(v.x, v.y);
    __half2 hi = __floats2half2_rn(v.z, v.w);
    uint2 u;
    u.x = *reinterpret_cast<uint32_t*>(&lo);
    u.y = *reinterpret_cast<uint32_t*>(&hi);
    *reinterpret_cast<uint2*>(dst) = u;
}

// ---------------------------------------------------------------------------
// Weight fp32 -> fp16 conversion (4 x 512 x 512)
// ---------------------------------------------------------------------------
__global__ __launch_bounds__(256) void w2h_kernel(const float* __restrict__ wq,
                                                  const float* __restrict__ wk,
                                                  const float* __restrict__ wv,
                                                  const float* __restrict__ wp,
                                                  __half* __restrict__ dst)
{
    const int gid = blockIdx.x * 256 + threadIdx.x;
    const int mat = gid >> 16;
    const int off = (gid & 65535) * 4;
    const float* src = (mat == 0) ? wq : (mat == 1) ? wk : (mat == 2) ? wv : wp;
    float4 v = *reinterpret_cast<const float4*>(src + off);
    st_h4(&dst[(long)mat * C_ * C_ + off], v);
}

// ---------------------------------------------------------------------------
// GroupNorm -> fp16 output
// ---------------------------------------------------------------------------
__global__ __launch_bounds__(256) void gn_kernel(const float* __restrict__ x,
                                                 const float* __restrict__ gamma,
                                                 const float* __restrict__ beta,
                                                 __half* __restrict__ hn)
{
    const int b = blockIdx.x >> 5;
    const int g = blockIdx.x & 31;
    const long base = ((long)b * C_ + (long)g * CPG) * H_;
    const float4* xp = reinterpret_cast<const float4*>(x + base);
    const int NE4 = CPG * H_ / 4;
    const int tid = threadIdx.x;

    float s = 0.f, ss = 0.f;
    for (int i = tid; i < NE4; i += 256) {
        float4 v = xp[i];
        s  += v.x + v.y + v.z + v.w;
        ss += v.x*v.x + v.y*v.y + v.z*v.z + v.w*v.w;
    }
    __shared__ float rs[8], rss[8];
    #pragma unroll
    for (int o = 16; o > 0; o >>= 1) {
        s  += __shfl_down_sync(0xFFFFFFFFu, s,  o);
        ss += __shfl_down_sync(0xFFFFFFFFu, ss, o);
    }
    if ((tid & 31) == 0) { rs[tid >> 5] = s; rss[tid >> 5] = ss; }
    __syncthreads();
    if (tid < 32) {
        s  = (tid < 8) ? rs[tid]  : 0.f;
        ss = (tid < 8) ? rss[tid] : 0.f;
        #pragma unroll
        for (int o = 4; o > 0; o >>= 1) {
            s  += __shfl_down_sync(0xFFFFFFFFu, s,  o);
            ss += __shfl_down_sync(0xFFFFFFFFu, ss, o);
        }
        if (tid == 0) { rs[0] = s; rss[0] = ss; }
    }
    __syncthreads();
    const float mean = rs[0] * (1.f / (CPG * H_));
    const float var  = rss[0] * (1.f / (CPG * H_)) - mean * mean;
    const float inv  = rsqrtf(var + 1e-6f);

    for (int i = tid; i < NE4; i += 256) {
        const int c = g * CPG + (i * 4) / H_;
        const float gm = gamma[c] * inv;
        const float bt = beta[c] - mean * gm;
        float4 v = xp[i];
        float4 o;
        o.x = v.x * gm + bt; o.y = v.y * gm + bt;
        o.z = v.z * gm + bt; o.w = v.w * gm + bt;
        st_h4(&hn[base + (long)i * 4], o);
    }
}

// ---------------------------------------------------------------------------
// Row softmax over last dim (2048), fp16 in/out, fp32 math.
// ---------------------------------------------------------------------------
__global__ __launch_bounds__(256) void softmax_kernel(__half* __restrict__ w)
{
    uint4* row = reinterpret_cast<uint4*>(w + (long)blockIdx.x * H_);
    const int tid = threadIdx.x;
    uint4 u = row[tid];
    __half2* hp = reinterpret_cast<__half2*>(&u);
    float f[8];
    #pragma unroll
    for (int i = 0; i < 4; i++) {
        float2 p = __half22float2(hp[i]);
        f[2*i] = p.x; f[2*i+1] = p.y;
    }

    float m = f[0];
    #pragma unroll
    for (int i = 1; i < 8; i++) m = fmaxf(m, f[i]);
    __shared__ float red[8];
    #pragma unroll
    for (int o = 16; o > 0; o >>= 1) m = fmaxf(m, __shfl_xor_sync(0xFFFFFFFFu, m, o));
    if ((tid & 31) == 0) red[tid >> 5] = m;
    __syncthreads();
    if (tid < 32) {
        m = (tid < 8) ? red[tid] : -1e30f;
        #pragma unroll
        for (int o = 4; o > 0; o >>= 1) m = fmaxf(m, __shfl_xor_sync(0xFFFFFFFFu, m, o));
        if (tid == 0) red[0] = m;
    }
    __syncthreads();
    m = red[0];

    float s = 0.f;
    #pragma unroll
    for (int i = 0; i < 8; i++) { f[i] = expf(f[i] - m); s += f[i]; }
    __shared__ float red2[8];
    #pragma unroll
    for (int o = 16; o > 0; o >>= 1) s += __shfl_xor_sync(0xFFFFFFFFu, s, o);
    if ((tid & 31) == 0) red2[tid >> 5] = s;
    __syncthreads();
    if (tid < 32) {
        s = (tid < 8) ? red2[tid] : 0.f;
        #pragma unroll
        for (int o = 4; o > 0; o >>= 1) s += __shfl_xor_sync(0xFFFFFFFFu, s, o);
        if (tid == 0) red2[0] = s;
    }
    __syncthreads();
    const float r = 1.f / red2[0];
    #pragma unroll
    for (int i = 0; i < 4; i++)
        hp[i] = __floats2half2_rn(f[2*i] * r, f[2*i+1] * r);
    row[tid] = u;
}

// ---------------------------------------------------------------------------
// Tensor-core fp16 GEMM, 4-stage cp.async pipeline, one barrier per k-tile.
//   C[m,n] = alpha * sum_k A(m,k)*B(k,n) + bias[m] (+resid fp32)
//   TA=false: A gmem [m][k]   TA=true: A gmem [k][m]
//   TB=false: B gmem [k][n]   TB=true: B gmem [n][k]
// Tiles: BM=BN=128, BK=32, 4 stages. 8 warps (2x4), 64x32 per warp.
// ---------------------------------------------------------------------------
#define BM 128
#define BN 128
#define BK 32
#define NSTAGE 4
#define PA 40    // pitch (halves) m/n-major rows: 80B
#define PK 136   // pitch (halves) k-major rows:   272B

__device__ __forceinline__ void cp16(void* s, const void* g) {
    asm volatile("cp.async.cg.shared.global [%0], [%1], 16;"
                 :: "r"(smem_u32(s)), "l"(g));
}
__device__ __forceinline__ void cp_commit() { asm volatile("cp.async.commit_group;"); }
__device__ __forceinline__ void cp_wait2() { asm volatile("cp.async.wait_group 2;"); }
__device__ __forceinline__ void cp_wait0() { asm volatile("cp.async.wait_group 0;"); }

__device__ __forceinline__ void ldsm4(uint32_t* r, uint32_t a) {
    asm volatile("ldmatrix.sync.aligned.m8n8.x4.shared.b16 {%0,%1,%2,%3}, [%4];"
                 : "=r"(r[0]), "=r"(r[1]), "=r"(r[2]), "=r"(r[3]) : "r"(a));
}
__device__ __forceinline__ void ldsm4t(uint32_t* r, uint32_t a) {
    asm volatile("ldmatrix.sync.aligned.m8n8.x4.trans.shared.b16 {%0,%1,%2,%3}, [%4];"
                 : "=r"(r[0]), "=r"(r[1]), "=r"(r[2]), "=r"(r[3]) : "r"(a));
}
__device__ __forceinline__ void ldsm2(uint32_t* r, uint32_t a) {
    asm volatile("ldmatrix.sync.aligned.m8n8.x2.shared.b16 {%0,%1}, [%2];"
                 : "=r"(r[0]), "=r"(r[1]) : "r"(a));
}
__device__ __forceinline__ void ldsm2t(uint32_t* r, uint32_t a) {
    asm volatile("ldmatrix.sync.aligned.m8n8.x2.trans.shared.b16 {%0,%1}, [%2];"
                 : "=r"(r[0]), "=r"(r[1]) : "r"(a));
}
__device__ __forceinline__ void mma16816(float* c, const uint32_t* a, const uint32_t* b) {
    asm volatile("mma.sync.aligned.m16n8k16.row.col.f32.f16.f16.f32 "
                 "{%0,%1,%2,%3}, {%4,%5,%6,%7}, {%8,%9}, {%0,%1,%2,%3};"
                 : "+f"(c[0]), "+f"(c[1]), "+f"(c[2]), "+f"(c[3])
                 : "r"(a[0]), "r"(a[1]), "r"(a[2]), "r"(a[3]), "r"(b[0]), "r"(b[1]));
}
__device__ __forceinline__ void store2(float* p, float x, float y) {
    *reinterpret_cast<float2*>(p) = make_float2(x, y);
}
__device__ __forceinline__ void store2(__half* p, float x, float y) {
    *reinterpret_cast<__half2*>(p) = __floats2half2_rn(x, y);
}

template<bool TA, bool TB, typename OutT>
__global__ __launch_bounds__(256, 2) void hgemm_kernel(
    const __half* __restrict__ Ab, const __half* __restrict__ Bb, OutT* __restrict__ Cb,
    int K, int lda, int ldb, int ldc,
    long sA, long sB, long sC,
    const float* __restrict__ bias, float alpha,
    const float* __restrict__ resid, long sR)
{
    constexpr int ASZ = TA ? (BK * PK) : (BM * PA);
    constexpr int BSZ = TB ? (BN * PA) : (BK * PK);
    constexpr int STG = ASZ + BSZ;
    extern __shared__ __align__(16) __half sm[];

    const int tid = threadIdx.x;
    const int bz = blockIdx.z;
    const __half* A = Ab + (long)bz * sA;
    const __half* B = Bb + (long)bz * sB;
    OutT* C = Cb + (long)bz * sC;
    const int m0 = blockIdx.y * BM;
    const int n0 = blockIdx.x * BN;

    const int wid = tid >> 5, lane = tid & 31;
    const int wm = (wid & 1) * 64;
    const int wn = (wid >> 1) * 32;

    float acc[4][4][4] = {};

    auto stage = [&](int k0, int buf) {
        __half* As = sm + buf * STG;
        __half* Bs = As + ASZ;
        #pragma unroll
        for (int i = 0; i < 2; i++) {
            const int c = tid + i * 256;
            if (!TA) {
                const int row = c >> 2, kc = c & 3;
                cp16(&As[row * PA + kc * 8],
                     &A[(long)(m0 + row) * lda + k0 + kc * 8]);
            } else {
                const int row = c >> 4, mc = c & 15;
                cp16(&As[row * PK + mc * 8],
                     &A[(long)(k0 + row) * lda + m0 + mc * 8]);
            }
        }
        #pragma unroll
        for (int i = 0; i < 2; i++) {
            const int c = tid + i * 256;
            if (!TB) {
                const int row = c >> 4, nc = c & 15;
                cp16(&Bs[row * PK + nc * 8],
                     &B[(long)(k0 + row) * ldb + n0 + nc * 8]);
            } else {
                const int row = c >> 2, kc = c & 3;
                cp16(&Bs[row * PA + kc * 8],
                     &B[(long)(n0 + row) * ldb + k0 + kc * 8]);
            }
        }
        cp_commit();
    };

    // prologue: stage tiles 0..2
    stage(0, 0);
    stage(BK, 1);
    stage(2 * BK, 2);

    const int T = K / BK;
    for (int t = 0; t < T; t++) {
        cp_wait2();              // tile t resident
        __syncthreads();         // all warps done with tile t-1; tile t visible
        if (t + 3 < T) stage((t + 3) * BK, (t + 3) & 3);

        const int buf = t & 3;
        const __half* As = sm + buf * STG;
        const __half* Bs = As + ASZ;

        #pragma unroll
        for (int ks = 0; ks < BK; ks += 16) {
            uint32_t a[4][4], b[4][2];
            #pragma unroll
            for (int mt = 0; mt < 4; mt++) {
                if (!TA) {
                    const int row = wm + mt * 16 + (lane & 15);
                    ldsm4(a[mt], smem_u32(&As[row * PA + ks + (lane >> 4) * 8]));
                } else {
                    const int kk = ks + (lane >> 4) * 8 + (lane & 7);
                    const int mm = wm + mt * 16 + ((lane >> 3) & 1) * 8;
                    ldsm4t(a[mt], smem_u32(&As[kk * PK + mm]));
                }
            }
            #pragma unroll
            for (int nt = 0; nt < 4; nt++) {
                const int l = lane & 15;
                if (!TB) {
                    const int kk = ks + l;
                    ldsm2t(b[nt], smem_u32(&Bs[kk * PK + wn + nt * 8]));
                } else {
                    const int nn = wn + nt * 8 + (l & 7);
                    ldsm2(b[nt], smem_u32(&Bs[nn * PA + ks + (l >> 3) * 8]));
                }
            }
            #pragma unroll
            for (int mt = 0; mt < 4; mt++)
                #pragma unroll
                for (int nt = 0; nt < 4; nt++)
                    mma16816(acc[mt][nt], a[mt], b[nt]);
        }
    }
    cp_wait0();

    // ---- epilogue ----
    const int r0 = m0 + wm + (lane >> 2);
    const int c0 = n0 + wn + (lane & 3) * 2;
    #pragma unroll
    for (int mt = 0; mt < 4; mt++) {
        #pragma unroll
        for (int nt = 0; nt < 4; nt++) {
            const float* a4 = acc[mt][nt];
            const int r = r0 + mt * 16;
            const int c = c0 + nt * 8;
            #pragma unroll
            for (int h = 0; h < 2; h++) {
                const int rr = r + h * 8;
                const float bi = bias ? bias[rr] : 0.f;
                float vx = fmaf(a4[h * 2 + 0], alpha, bi);
                float vy = fmaf(a4[h * 2 + 1], alpha, bi);
                const long off = (long)rr * ldc + c;
                if (resid) {
                    const float2 rv = *reinterpret_cast<const float2*>(&resid[(long)bz * sR + off]);
                    vx += rv.x; vy += rv.y;
                }
                store2(&C[off], vx, vy);
            }
        }
    }
}

// ---------------------------------------------------------------------------
extern "C" void kernel_launch(void* const* d_in, const int* in_sizes, int n_in,
                              void* d_out, int out_size)
{
    const float* x     = (const float*)d_in[0];
    const float* gamma = (const float*)d_in[1];
    const float* beta  = (const float*)d_in[2];
    const float* wq    = (const float*)d_in[3];
    const float* bq    = (const float*)d_in[4];
    const float* wk    = (const float*)d_in[5];
    const float* bk    = (const float*)d_in[6];
    const float* wv    = (const float*)d_in[7];
    const float* bv    = (const float*)d_in[8];
    const float* wp    = (const float*)d_in[9];
    const float* bp    = (const float*)d_in[10];
    float* out = (float*)d_out;

    __half *hn, *q, *k, *v, *s, *w;
    cudaGetSymbolAddress((void**)&hn, g_hn);
    cudaGetSymbolAddress((void**)&q,  g_q);
    cudaGetSymbolAddress((void**)&k,  g_k);
    cudaGetSymbolAddress((void**)&v,  g_v);
    cudaGetSymbolAddress((void**)&s,  g_s);
    cudaGetSymbolAddress((void**)&w,  g_w);

    const long HH = (long)H_ * H_;
    const long CC = (long)C_ * C_;
    const float scale = 0.044194173824159216f;   // 1/sqrt(512)

    // dynamic smem sizes (bytes) per template config
    const int smNN = NSTAGE * ((BM * PA) + (BK * PK)) * 2;   // <false,false>
    const int smTN = NSTAGE * ((BK * PK) + (BK * PK)) * 2;   // <true,false>
    const int smNT = NSTAGE * ((BM * PA) + (BN * PA)) * 2;   // <false,true>
    cudaFuncSetAttribute(hgemm_kernel<false, false, __half>, cudaFuncAttributeMaxDynamicSharedMemorySize, smNN);
    cudaFuncSetAttribute(hgemm_kernel<false, false, float >, cudaFuncAttributeMaxDynamicSharedMemorySize, smNN);
    cudaFuncSetAttribute(hgemm_kernel<true,  false, __half>, cudaFuncAttributeMaxDynamicSharedMemorySize, smTN);
    cudaFuncSetAttribute(hgemm_kernel<false, true,  __half>, cudaFuncAttributeMaxDynamicSharedMemorySize, smNT);

    // 0. weights -> fp16 ; 1. GroupNorm -> fp16
    w2h_kernel<<<1024, 256>>>(wq, wk, wv, wp, w);
    gn_kernel<<<B_ * G_, 256>>>(x, gamma, beta, hn);

    // 2-4. q/k/v = W @ hn_b + bias   (A=[m,k], B=[k,n])
    dim3 gqkv(H_ / BN, C_ / BM, B_);
    hgemm_kernel<false, false, __half><<<gqkv, 256, smNN>>>(w + 0*CC, hn, q, C_, C_, H_, H_,
                                                            0, CH, CH, bq, 1.f, nullptr, 0);
    hgemm_kernel<false, false, __half><<<gqkv, 256, smNN>>>(w + 1*CC, hn, k, C_, C_, H_, H_,
                                                            0, CH, CH, bk, 1.f, nullptr, 0);
    hgemm_kernel<false, false, __half><<<gqkv, 256, smNN>>>(w + 2*CC, hn, v, C_, C_, H_, H_,
                                                            0, CH, CH, bv, 1.f, nullptr, 0);

    // 5. scores s[b,i,j] = scale * sum_c q[b,c,i] k[b,c,j]   (A=[k,m], B=[k,n])
    dim3 gsc(H_ / BN, H_ / BM, B_);
    hgemm_kernel<true, false, __half><<<gsc, 256, smTN>>>(q, k, s, C_, H_, H_, H_,
                                                          CH, CH, HH, nullptr, scale, nullptr, 0);

    // 6. softmax over j
    softmax_kernel<<<B_ * H_, 256>>>(s);

    // 7. h_[b,c,i] = sum_j v[b,c,j] p[i,j]   (A=[m,k], B=[n,k]) -> reuse g_hn
    dim3 gav(H_ / BN, C_ / BM, B_);
    hgemm_kernel<false, true, __half><<<gav, 256, smNT>>>(v, s, hn, H_, H_, H_, H_,
                                                          CH, HH, CH, nullptr, 1.f, nullptr, 0);

    // 8. out = x + Wp @ h_ + bp  (fp32 out, residual)
    hgemm_kernel<false, false, float><<<gqkv, 256, smNN>>>(w + 3*CC, hn, out, C_, C_, H_, H_,
                                                           0, CH, CH, bp, 1.f, x, CH);
}

// round 7
// speedup vs baseline: 7.1641x; 1.1547x over previous
#include <cuda_runtime.h>
#include <cuda_fp16.h>
#include <math.h>
#include <stdint.h>

#define B_ 8
#define C_ 512
#define H_ 2048
#define G_ 32
#define CPG 16
static const long CH = (long)C_ * H_;

// Scratch (device globals: allocation-free contract). All fp16 intermediates.
__device__ __half g_hn[B_*C_*H_];        // GN output; later reused for attn*V output
__device__ __half g_q [B_*C_*H_];
__device__ __half g_k [B_*C_*H_];
__device__ __half g_v [B_*C_*H_];
__device__ __half g_s [(long)B_*H_*H_]; // attention scores/probs (64 MB fp16)
__device__ __half g_w [4*C_*C_];        // fp16 weights: wq,wk,wv,wp

__device__ __forceinline__ uint32_t smem_u32(const void* p) {
    return (uint32_t)__cvta_generic_to_shared(p);
}
__device__ __forceinline__ void st_h4(__half* dst, float4 v) {
    __half2 lo = __floats2half2_rn(v.x, v.y);
    __half2 hi = __floats2half2_rn(v.z, v.w);
    uint2 u;
    u.x = *reinterpret_cast<uint32_t*>(&lo);
    u.y = *reinterpret_cast<uint32_t*>(&hi);
    *reinterpret_cast<uint2*>(dst) = u;
}

// ---------------------------------------------------------------------------
// Weight fp32 -> fp16 conversion (4 x 512 x 512)
// ---------------------------------------------------------------------------
__global__ __launch_bounds__(256) void w2h_kernel(const float* __restrict__ wq,
                                                  const float* __restrict__ wk,
                                                  const float* __restrict__ wv,
                                                  const float* __restrict__ wp,
                                                  __half* __restrict__ dst)
{
    const int gid = blockIdx.x * 256 + threadIdx.x;
    const int mat = gid >> 16;
    const int off = (gid & 65535) * 4;
    const float* src = (mat == 0) ? wq : (mat == 1) ? wk : (mat == 2) ? wv : wp;
    float4 v = *reinterpret_cast<const float4*>(src + off);
    st_h4(&dst[(long)mat * C_ * C_ + off], v);
}

// ---------------------------------------------------------------------------
// GroupNorm -> fp16 output
// ---------------------------------------------------------------------------
__global__ __launch_bounds__(256) void gn_kernel(const float* __restrict__ x,
                                                 const float* __restrict__ gamma,
                                                 const float* __restrict__ beta,
                                                 __half* __restrict__ hn)
{
    const int b = blockIdx.x >> 5;
    const int g = blockIdx.x & 31;
    const long base = ((long)b * C_ + (long)g * CPG) * H_;
    const float4* xp = reinterpret_cast<const float4*>(x + base);
    const int NE4 = CPG * H_ / 4;
    const int tid = threadIdx.x;

    float s = 0.f, ss = 0.f;
    for (int i = tid; i < NE4; i += 256) {
        float4 v = xp[i];
        s  += v.x + v.y + v.z + v.w;
        ss += v.x*v.x + v.y*v.y + v.z*v.z + v.w*v.w;
    }
    __shared__ float rs[8], rss[8];
    #pragma unroll
    for (int o = 16; o > 0; o >>= 1) {
        s  += __shfl_down_sync(0xFFFFFFFFu, s,  o);
        ss += __shfl_down_sync(0xFFFFFFFFu, ss, o);
    }
    if ((tid & 31) == 0) { rs[tid >> 5] = s; rss[tid >> 5] = ss; }
    __syncthreads();
    if (tid < 32) {
        s  = (tid < 8) ? rs[tid]  : 0.f;
        ss = (tid < 8) ? rss[tid] : 0.f;
        #pragma unroll
        for (int o = 4; o > 0; o >>= 1) {
            s  += __shfl_down_sync(0xFFFFFFFFu, s,  o);
            ss += __shfl_down_sync(0xFFFFFFFFu, ss, o);
        }
        if (tid == 0) { rs[0] = s; rss[0] = ss; }
    }
    __syncthreads();
    const float mean = rs[0] * (1.f / (CPG * H_));
    const float var  = rss[0] * (1.f / (CPG * H_)) - mean * mean;
    const float inv  = rsqrtf(var + 1e-6f);

    for (int i = tid; i < NE4; i += 256) {
        const int c = g * CPG + (i * 4) / H_;
        const float gm = gamma[c] * inv;
        const float bt = beta[c] - mean * gm;
        float4 v = xp[i];
        float4 o;
        o.x = v.x * gm + bt; o.y = v.y * gm + bt;
        o.z = v.z * gm + bt; o.w = v.w * gm + bt;
        st_h4(&hn[base + (long)i * 4], o);
    }
}

// ---------------------------------------------------------------------------
// Row softmax over last dim (2048), fp16 in/out, fp32 math.
// ---------------------------------------------------------------------------
__global__ __launch_bounds__(256) void softmax_kernel(__half* __restrict__ w)
{
    uint4* row = reinterpret_cast<uint4*>(w + (long)blockIdx.x * H_);
    const int tid = threadIdx.x;
    uint4 u = row[tid];
    __half2* hp = reinterpret_cast<__half2*>(&u);
    float f[8];
    #pragma unroll
    for (int i = 0; i < 4; i++) {
        float2 p = __half22float2(hp[i]);
        f[2*i] = p.x; f[2*i+1] = p.y;
    }

    float m = f[0];
    #pragma unroll
    for (int i = 1; i < 8; i++) m = fmaxf(m, f[i]);
    __shared__ float red[8];
    #pragma unroll
    for (int o = 16; o > 0; o >>= 1) m = fmaxf(m, __shfl_xor_sync(0xFFFFFFFFu, m, o));
    if ((tid & 31) == 0) red[tid >> 5] = m;
    __syncthreads();
    if (tid < 32) {
        m = (tid < 8) ? red[tid] : -1e30f;
        #pragma unroll
        for (int o = 4; o > 0; o >>= 1) m = fmaxf(m, __shfl_xor_sync(0xFFFFFFFFu, m, o));
        if (tid == 0) red[0] = m;
    }
    __syncthreads();
    m = red[0];

    float s = 0.f;
    #pragma unroll
    for (int i = 0; i < 8; i++) { f[i] = expf(f[i] - m); s += f[i]; }
    __shared__ float red2[8];
    #pragma unroll
    for (int o = 16; o > 0; o >>= 1) s += __shfl_xor_sync(0xFFFFFFFFu, s, o);
    if ((tid & 31) == 0) red2[tid >> 5] = s;
    __syncthreads();
    if (tid < 32) {
        s = (tid < 8) ? red2[tid] : 0.f;
        #pragma unroll
        for (int o = 4; o > 0; o >>= 1) s += __shfl_xor_sync(0xFFFFFFFFu, s, o);
        if (tid == 0) red2[0] = s;
    }
    __syncthreads();
    const float r = 1.f / red2[0];
    #pragma unroll
    for (int i = 0; i < 4; i++)
        hp[i] = __floats2half2_rn(f[2*i] * r, f[2*i+1] * r);
    row[tid] = u;
}

// ---------------------------------------------------------------------------
// Tensor-core fp16 GEMM, XOR-swizzled conflict-free smem, BK=64, 3 stages.
//   C[m,n] = alpha * sum_k A(m,k)*B(k,n) + bias[m] (+resid fp32)
//   TA=false: A gmem [m][k]   TA=true: A gmem [k][m]
//   TB=false: B gmem [k][n]   TB=true: B gmem [n][k]
// Smem layouts (16B chunks, swizzle chunk^=(row&7) within 8-chunk groups):
//   row128 : 128 rows x 128B (8 chunks)   for A(!TA), B(TB)
//   kmaj256:  64 rows x 256B (16 chunks)  for A(TA),  B(!TB)
// Both are 16 KB; stage = A+B = 32 KB; 3 stages = 96 KB.
// 8 warps (2x4), warp tile 64x32, one __syncthreads per 64-wide k-tile.
// ---------------------------------------------------------------------------
#define BM 128
#define BN 128
#define BK 64
#define NSTAGE 3
#define STG_BYTES 32768
#define GEMM_SMEM (NSTAGE * STG_BYTES)

__device__ __forceinline__ void cp16(uint32_t s, const void* g) {
    asm volatile("cp.async.cg.shared.global [%0], [%1], 16;" :: "r"(s), "l"(g));
}
__device__ __forceinline__ void cp_commit() { asm volatile("cp.async.commit_group;"); }
__device__ __forceinline__ void cp_wait1() { asm volatile("cp.async.wait_group 1;"); }
__device__ __forceinline__ void cp_wait0() { asm volatile("cp.async.wait_group 0;"); }

__device__ __forceinline__ void ldsm4(uint32_t* r, uint32_t a) {
    asm volatile("ldmatrix.sync.aligned.m8n8.x4.shared.b16 {%0,%1,%2,%3}, [%4];"
                 : "=r"(r[0]), "=r"(r[1]), "=r"(r[2]), "=r"(r[3]) : "r"(a));
}
__device__ __forceinline__ void ldsm4t(uint32_t* r, uint32_t a) {
    asm volatile("ldmatrix.sync.aligned.m8n8.x4.trans.shared.b16 {%0,%1,%2,%3}, [%4];"
                 : "=r"(r[0]), "=r"(r[1]), "=r"(r[2]), "=r"(r[3]) : "r"(a));
}
__device__ __forceinline__ void mma16816(float* c, const uint32_t* a, const uint32_t* b) {
    asm volatile("mma.sync.aligned.m16n8k16.row.col.f32.f16.f16.f32 "
                 "{%0,%1,%2,%3}, {%4,%5,%6,%7}, {%8,%9}, {%0,%1,%2,%3};"
                 : "+f"(c[0]), "+f"(c[1]), "+f"(c[2]), "+f"(c[3])
                 : "r"(a[0]), "r"(a[1]), "r"(a[2]), "r"(a[3]), "r"(b[0]), "r"(b[1]));
}
__device__ __forceinline__ void store2(float* p, float x, float y) {
    *reinterpret_cast<float2*>(p) = make_float2(x, y);
}
__device__ __forceinline__ void store2(__half* p, float x, float y) {
    *reinterpret_cast<__half2*>(p) = __floats2half2_rn(x, y);
}

template<bool TA, bool TB, typename OutT>
__global__ __launch_bounds__(256, 2) void hgemm_kernel(
    const __half* __restrict__ Ab, const __half* __restrict__ Bb, OutT* __restrict__ Cb,
    int K, int lda, int ldb, int ldc,
    long sA, long sB, long sC,
    const float* __restrict__ bias, float alpha,
    const float* __restrict__ resid, long sR)
{
    extern __shared__ __align__(128) char sm[];
    const uint32_t smb = smem_u32(sm);

    const int tid = threadIdx.x;
    const int bz = blockIdx.z;
    const __half* A = Ab + (long)bz * sA;
    const __half* B = Bb + (long)bz * sB;
    OutT* C = Cb + (long)bz * sC;
    const int m0 = blockIdx.y * BM;
    const int n0 = blockIdx.x * BN;

    const int wid = tid >> 5, lane = tid & 31;
    const int wm = (wid & 1) * 64;
    const int wn = (wid >> 1) * 32;

    float acc[4][4][4] = {};

    // ---- staging: 1024 16B-chunks per operand tile, 4 per thread ----
    auto stage = [&](int k0, int buf) {
        const uint32_t ab = smb + buf * STG_BYTES;
        const uint32_t bb = ab + 16384;
        #pragma unroll
        for (int i = 0; i < 4; i++) {
            const int c = tid + i * 256;
            if (!TA) {
                const int row = c >> 3, ch = c & 7;
                const int sw = ch ^ (row & 7);
                cp16(ab + row * 128 + sw * 16,
                     &A[(long)(m0 + row) * lda + k0 + ch * 8]);
            } else {
                const int row = c >> 4, ch = c & 15;
                const int sw = (ch & 8) | ((ch ^ row) & 7);
                cp16(ab + row * 256 + sw * 16,
                     &A[(long)(k0 + row) * lda + m0 + ch * 8]);
            }
        }
        #pragma unroll
        for (int i = 0; i < 4; i++) {
            const int c = tid + i * 256;
            if (!TB) {
                const int row = c >> 4, ch = c & 15;
                const int sw = (ch & 8) | ((ch ^ row) & 7);
                cp16(bb + row * 256 + sw * 16,
                     &B[(long)(k0 + row) * ldb + n0 + ch * 8]);
            } else {
                const int row = c >> 3, ch = c & 7;
                const int sw = ch ^ (row & 7);
                cp16(bb + row * 128 + sw * 16,
                     &B[(long)(n0 + row) * ldb + k0 + ch * 8]);
            }
        }
        cp_commit();
    };

    stage(0, 0);
    stage(BK, 1);

    const int T = K / BK;
    for (int t = 0; t < T; t++) {
        cp_wait1();              // tile t resident (only tile t+1's group may be in flight)
        __syncthreads();         // all warps done with tile t-1
        if (t + 2 < T) stage((t + 2) * BK, (t + 2) % NSTAGE);

        const uint32_t ab = smb + (t % NSTAGE) * STG_BYTES;
        const uint32_t bb = ab + 16384;

        #pragma unroll
        for (int ks = 0; ks < BK; ks += 16) {
            uint32_t a[4][4], b[4][2];
            // ---- A fragments: 4x ldsm4 ----
            #pragma unroll
            for (int mt = 0; mt < 4; mt++) {
                if (!TA) {
                    const int row = wm + mt * 16 + (lane & 15);
                    const int ch = (ks >> 3) + (lane >> 4);
                    const int sw = ch ^ (row & 7);
                    ldsm4(a[mt], ab + row * 128 + sw * 16);
                } else {
                    const int kk = ks + (lane >> 4) * 8 + (lane & 7);
                    const int mm = wm + mt * 16 + ((lane >> 3) & 1) * 8;
                    const int ch = mm >> 3;
                    const int sw = (ch & 8) | ((ch ^ kk) & 7);
                    ldsm4t(a[mt], ab + kk * 256 + sw * 16);
                }
            }
            // ---- B fragments: 2x ldsm4 (two 8-col groups each) ----
            #pragma unroll
            for (int nt2 = 0; nt2 < 2; nt2++) {
                uint32_t r[4];
                if (!TB) {
                    const int kk = ks + ((lane >> 3) & 1) * 8 + (lane & 7);
                    const int ncol = wn + nt2 * 16 + ((lane >> 4) & 1) * 8;
                    const int ch = ncol >> 3;
                    const int sw = (ch & 8) | ((ch ^ kk) & 7);
                    ldsm4t(r, bb + kk * 256 + sw * 16);
                } else {
                    const int nn = wn + nt2 * 16 + ((lane >> 4) & 1) * 8 + (lane & 7);
                    const int ch = (ks >> 3) + ((lane >> 3) & 1);
                    const int sw = ch ^ (nn & 7);
                    ldsm4(r, bb + nn * 128 + sw * 16);
                }
                b[2*nt2][0] = r[0]; b[2*nt2][1] = r[1];
                b[2*nt2+1][0] = r[2]; b[2*nt2+1][1] = r[3];
            }
            #pragma unroll
            for (int mt = 0; mt < 4; mt++)
                #pragma unroll
                for (int nt = 0; nt < 4; nt++)
                    mma16816(acc[mt][nt], a[mt], b[nt]);
        }
    }
    cp_wait0();

    // ---- epilogue ----
    const int r0 = m0 + wm + (lane >> 2);
    const int c0 = n0 + wn + (lane & 3) * 2;
    #pragma unroll
    for (int mt = 0; mt < 4; mt++) {
        #pragma unroll
        for (int nt = 0; nt < 4; nt++) {
            const float* a4 = acc[mt][nt];
            const int r = r0 + mt * 16;
            const int c = c0 + nt * 8;
            #pragma unroll
            for (int h = 0; h < 2; h++) {
                const int rr = r + h * 8;
                const float bi = bias ? bias[rr] : 0.f;
                float vx = fmaf(a4[h * 2 + 0], alpha, bi);
                float vy = fmaf(a4[h * 2 + 1], alpha, bi);
                const long off = (long)rr * ldc + c;
                if (resid) {
                    const float2 rv = *reinterpret_cast<const float2*>(&resid[(long)bz * sR + off]);
                    vx += rv.x; vy += rv.y;
                }
                store2(&C[off], vx, vy);
            }
        }
    }
}

// ---------------------------------------------------------------------------
extern "C" void kernel_launch(void* const* d_in, const int* in_sizes, int n_in,
                              void* d_out, int out_size)
{
    const float* x     = (const float*)d_in[0];
    const float* gamma = (const float*)d_in[1];
    const float* beta  = (const float*)d_in[2];
    const float* wq    = (const float*)d_in[3];
    const float* bq    = (const float*)d_in[4];
    const float* wk    = (const float*)d_in[5];
    const float* bk    = (const float*)d_in[6];
    const float* wv    = (const float*)d_in[7];
    const float* bv    = (const float*)d_in[8];
    const float* wp    = (const float*)d_in[9];
    const float* bp    = (const float*)d_in[10];
    float* out = (float*)d_out;

    __half *hn, *q, *k, *v, *s, *w;
    cudaGetSymbolAddress((void**)&hn, g_hn);
    cudaGetSymbolAddress((void**)&q,  g_q);
    cudaGetSymbolAddress((void**)&k,  g_k);
    cudaGetSymbolAddress((void**)&v,  g_v);
    cudaGetSymbolAddress((void**)&s,  g_s);
    cudaGetSymbolAddress((void**)&w,  g_w);

    const long HH = (long)H_ * H_;
    const long CC = (long)C_ * C_;
    const float scale = 0.044194173824159216f;   // 1/sqrt(512)

    cudaFuncSetAttribute(hgemm_kernel<false, false, __half>, cudaFuncAttributeMaxDynamicSharedMemorySize, GEMM_SMEM);
    cudaFuncSetAttribute(hgemm_kernel<false, false, float >, cudaFuncAttributeMaxDynamicSharedMemorySize, GEMM_SMEM);
    cudaFuncSetAttribute(hgemm_kernel<true,  false, __half>, cudaFuncAttributeMaxDynamicSharedMemorySize, GEMM_SMEM);
    cudaFuncSetAttribute(hgemm_kernel<false, true,  __half>, cudaFuncAttributeMaxDynamicSharedMemorySize, GEMM_SMEM);

    // 0. weights -> fp16 ; 1. GroupNorm -> fp16
    w2h_kernel<<<1024, 256>>>(wq, wk, wv, wp, w);
    gn_kernel<<<B_ * G_, 256>>>(x, gamma, beta, hn);

    // 2-4. q/k/v = W @ hn_b + bias   (A=[m,k], B=[k,n])
    dim3 gqkv(H_ / BN, C_ / BM, B_);
    hgemm_kernel<false, false, __half><<<gqkv, 256, GEMM_SMEM>>>(w + 0*CC, hn, q, C_, C_, H_, H_,
                                                                 0, CH, CH, bq, 1.f, nullptr, 0);
    hgemm_kernel<false, false, __half><<<gqkv, 256, GEMM_SMEM>>>(w + 1*CC, hn, k, C_, C_, H_, H_,
                                                                 0, CH, CH, bk, 1.f, nullptr, 0);
    hgemm_kernel<false, false, __half><<<gqkv, 256, GEMM_SMEM>>>(w + 2*CC, hn, v, C_, C_, H_, H_,
                                                                 0, CH, CH, bv, 1.f, nullptr, 0);

    // 5. scores s[b,i,j] = scale * sum_c q[b,c,i] k[b,c,j]   (A=[k,m], B=[k,n])
    dim3 gsc(H_ / BN, H_ / BM, B_);
    hgemm_kernel<true, false, __half><<<gsc, 256, GEMM_SMEM>>>(q, k, s, C_, H_, H_, H_,
                                                               CH, CH, HH, nullptr, scale, nullptr, 0);

    // 6. softmax over j
    softmax_kernel<<<B_ * H_, 256>>>(s);

    // 7. h_[b,c,i] = sum_j v[b,c,j] p[i,j]   (A=[m,k], B=[n,k]) -> reuse g_hn
    dim3 gav(H_ / BN, C_ / BM, B_);
    hgemm_kernel<false, true, __half><<<gav, 256, GEMM_SMEM>>>(v, s, hn, H_, H_, H_, H_,
                                                               CH, HH, CH, nullptr, 1.f, nullptr, 0);

    // 8. out = x + Wp @ h_ + bp  (fp32 out, residual)
    hgemm_kernel<false, false, float><<<gqkv, 256, GEMM_SMEM>>>(w + 3*CC, hn, out, C_, C_, H_, H_,
                                                                0, CH, CH, bp, 1.f, x, CH);
}

// round 8
// speedup vs baseline: 7.1829x; 1.0026x over previous
#include <cuda_runtime.h>
#include <cuda_fp16.h>
#include <math.h>
#include <stdint.h>

#define B_ 8
#define C_ 512
#define H_ 2048
#define G_ 32
#define CPG 16
static const long CH = (long)C_ * H_;

// Scratch (device globals: allocation-free contract). All fp16 intermediates.
__device__ __half g_hn[B_*C_*H_];        // GN output; later reused for attn*V output
__device__ __half g_q [B_*C_*H_];
__device__ __half g_k [B_*C_*H_];
__device__ __half g_v [B_*C_*H_];
__device__ __half g_s [(long)B_*H_*H_]; // attention scores/probs (64 MB fp16)
__device__ __half g_w [4*C_*C_];        // fp16 weights: wq,wk,wv,wp

__device__ __forceinline__ uint32_t smem_u32(const void* p) {
    return (uint32_t)__cvta_generic_to_shared(p);
}
__device__ __forceinline__ void st_h4(__half* dst, float4 v) {
    __half2 lo = __floats2half2_rn(v.x, v.y);
    __half2 hi = __floats2half2_rn(v.z, v.w);
    uint2 u;
    u.x = *reinterpret_cast<uint32_t*>(&lo);
    u.y = *reinterpret_cast<uint32_t*>(&hi);
    *reinterpret_cast<uint2*>(dst) = u;
}

// ---------------------------------------------------------------------------
// Weight fp32 -> fp16 conversion (4 x 512 x 512)
// ---------------------------------------------------------------------------
__global__ __launch_bounds__(256) void w2h_kernel(const float* __restrict__ wq,
                                                  const float* __restrict__ wk,
                                                  const float* __restrict__ wv,
                                                  const float* __restrict__ wp,
                                                  __half* __restrict__ dst)
{
    const int gid = blockIdx.x * 256 + threadIdx.x;
    const int mat = gid >> 16;
    const int off = (gid & 65535) * 4;
    const float* src = (mat == 0) ? wq : (mat == 1) ? wk : (mat == 2) ? wv : wp;
    float4 v = *reinterpret_cast<const float4*>(src + off);
    st_h4(&dst[(long)mat * C_ * C_ + off], v);
}

// ---------------------------------------------------------------------------
// GroupNorm -> fp16 output
// ---------------------------------------------------------------------------
__global__ __launch_bounds__(256) void gn_kernel(const float* __restrict__ x,
                                                 const float* __restrict__ gamma,
                                                 const float* __restrict__ beta,
                                                 __half* __restrict__ hn)
{
    const int b = blockIdx.x >> 5;
    const int g = blockIdx.x & 31;
    const long base = ((long)b * C_ + (long)g * CPG) * H_;
    const float4* xp = reinterpret_cast<const float4*>(x + base);
    const int NE4 = CPG * H_ / 4;
    const int tid = threadIdx.x;

    float s = 0.f, ss = 0.f;
    for (int i = tid; i < NE4; i += 256) {
        float4 v = xp[i];
        s  += v.x + v.y + v.z + v.w;
        ss += v.x*v.x + v.y*v.y + v.z*v.z + v.w*v.w;
    }
    __shared__ float rs[8], rss[8];
    #pragma unroll
    for (int o = 16; o > 0; o >>= 1) {
        s  += __shfl_down_sync(0xFFFFFFFFu, s,  o);
        ss += __shfl_down_sync(0xFFFFFFFFu, ss, o);
    }
    if ((tid & 31) == 0) { rs[tid >> 5] = s; rss[tid >> 5] = ss; }
    __syncthreads();
    if (tid < 32) {
        s  = (tid < 8) ? rs[tid]  : 0.f;
        ss = (tid < 8) ? rss[tid] : 0.f;
        #pragma unroll
        for (int o = 4; o > 0; o >>= 1) {
            s  += __shfl_down_sync(0xFFFFFFFFu, s,  o);
            ss += __shfl_down_sync(0xFFFFFFFFu, ss, o);
        }
        if (tid == 0) { rs[0] = s; rss[0] = ss; }
    }
    __syncthreads();
    const float mean = rs[0] * (1.f / (CPG * H_));
    const float var  = rss[0] * (1.f / (CPG * H_)) - mean * mean;
    const float inv  = rsqrtf(var + 1e-6f);

    for (int i = tid; i < NE4; i += 256) {
        const int c = g * CPG + (i * 4) / H_;
        const float gm = gamma[c] * inv;
        const float bt = beta[c] - mean * gm;
        float4 v = xp[i];
        float4 o;
        o.x = v.x * gm + bt; o.y = v.y * gm + bt;
        o.z = v.z * gm + bt; o.w = v.w * gm + bt;
        st_h4(&hn[base + (long)i * 4], o);
    }
}

// ---------------------------------------------------------------------------
// Row softmax over last dim (2048), fp16 in/out, fp32 math.
// ---------------------------------------------------------------------------
__global__ __launch_bounds__(256) void softmax_kernel(__half* __restrict__ w)
{
    uint4* row = reinterpret_cast<uint4*>(w + (long)blockIdx.x * H_);
    const int tid = threadIdx.x;
    uint4 u = row[tid];
    __half2* hp = reinterpret_cast<__half2*>(&u);
    float f[8];
    #pragma unroll
    for (int i = 0; i < 4; i++) {
        float2 p = __half22float2(hp[i]);
        f[2*i] = p.x; f[2*i+1] = p.y;
    }

    float m = f[0];
    #pragma unroll
    for (int i = 1; i < 8; i++) m = fmaxf(m, f[i]);
    __shared__ float red[8];
    #pragma unroll
    for (int o = 16; o > 0; o >>= 1) m = fmaxf(m, __shfl_xor_sync(0xFFFFFFFFu, m, o));
    if ((tid & 31) == 0) red[tid >> 5] = m;
    __syncthreads();
    if (tid < 32) {
        m = (tid < 8) ? red[tid] : -1e30f;
        #pragma unroll
        for (int o = 4; o > 0; o >>= 1) m = fmaxf(m, __shfl_xor_sync(0xFFFFFFFFu, m, o));
        if (tid == 0) red[0] = m;
    }
    __syncthreads();
    m = red[0];

    float s = 0.f;
    #pragma unroll
    for (int i = 0; i < 8; i++) { f[i] = expf(f[i] - m); s += f[i]; }
    __shared__ float red2[8];
    #pragma unroll
    for (int o = 16; o > 0; o >>= 1) s += __shfl_xor_sync(0xFFFFFFFFu, s, o);
    if ((tid & 31) == 0) red2[tid >> 5] = s;
    __syncthreads();
    if (tid < 32) {
        s = (tid < 8) ? red2[tid] : 0.f;
        #pragma unroll
        for (int o = 4; o > 0; o >>= 1) s += __shfl_xor_sync(0xFFFFFFFFu, s, o);
        if (tid == 0) red2[0] = s;
    }
    __syncthreads();
    const float r = 1.f / red2[0];
    #pragma unroll
    for (int i = 0; i < 4; i++)
        hp[i] = __floats2half2_rn(f[2*i] * r, f[2*i+1] * r);
    row[tid] = u;
}

// ---------------------------------------------------------------------------
// Tensor-core fp16 GEMM. 128x256x64 CTA tile, 8 warps, warp tile 64x64.
//   C[m,n] = alpha * sum_k A(m,k)*B(k,n) + bias[m] (+resid fp32)
//   TA=false: A gmem [m][k]   TA=true: A gmem [k][m]
//   TB=false: B gmem [k][n]   TB=true: B gmem [n][k]
// Smem (16B chunks, XOR swizzle within 8-chunk/128B groups):
//   A !TA: 128 rows x 128B   A TA: 64 rows x 256B    (16 KB)
//   B !TB:  64 rows x 512B   B TB: 256 rows x 128B   (32 KB)
// 3 stages x 48 KB = 144 KB dynamic smem, 1 CTA/SM.
// ---------------------------------------------------------------------------
#define BM 128
#define BN 256
#define BK 64
#define NSTAGE 3
#define ASZ 16384
#define STG_BYTES 49152
#define GEMM_SMEM (NSTAGE * STG_BYTES)

__device__ __forceinline__ void cp16(uint32_t s, const void* g) {
    asm volatile("cp.async.cg.shared.global [%0], [%1], 16;" :: "r"(s), "l"(g));
}
__device__ __forceinline__ void cp_commit() { asm volatile("cp.async.commit_group;"); }
__device__ __forceinline__ void cp_wait1() { asm volatile("cp.async.wait_group 1;"); }
__device__ __forceinline__ void cp_wait0() { asm volatile("cp.async.wait_group 0;"); }

__device__ __forceinline__ void ldsm4(uint32_t* r, uint32_t a) {
    asm volatile("ldmatrix.sync.aligned.m8n8.x4.shared.b16 {%0,%1,%2,%3}, [%4];"
                 : "=r"(r[0]), "=r"(r[1]), "=r"(r[2]), "=r"(r[3]) : "r"(a));
}
__device__ __forceinline__ void ldsm4t(uint32_t* r, uint32_t a) {
    asm volatile("ldmatrix.sync.aligned.m8n8.x4.trans.shared.b16 {%0,%1,%2,%3}, [%4];"
                 : "=r"(r[0]), "=r"(r[1]), "=r"(r[2]), "=r"(r[3]) : "r"(a));
}
__device__ __forceinline__ void mma16816(float* c, const uint32_t* a, const uint32_t* b) {
    asm volatile("mma.sync.aligned.m16n8k16.row.col.f32.f16.f16.f32 "
                 "{%0,%1,%2,%3}, {%4,%5,%6,%7}, {%8,%9}, {%0,%1,%2,%3};"
                 : "+f"(c[0]), "+f"(c[1]), "+f"(c[2]), "+f"(c[3])
                 : "r"(a[0]), "r"(a[1]), "r"(a[2]), "r"(a[3]), "r"(b[0]), "r"(b[1]));
}
__device__ __forceinline__ void store2(float* p, float x, float y) {
    *reinterpret_cast<float2*>(p) = make_float2(x, y);
}
__device__ __forceinline__ void store2(__half* p, float x, float y) {
    *reinterpret_cast<__half2*>(p) = __floats2half2_rn(x, y);
}

template<bool TA, bool TB, typename OutT>
__global__ __launch_bounds__(256) void hgemm_kernel(
    const __half* __restrict__ Ab, const __half* __restrict__ Bb, OutT* __restrict__ Cb,
    int K, int lda, int ldb, int ldc,
    long sA, long sB, long sC,
    const float* __restrict__ bias, float alpha,
    const float* __restrict__ resid, long sR)
{
    extern __shared__ __align__(128) char sm[];
    const uint32_t smb = smem_u32(sm);

    const int tid = threadIdx.x;
    const int bz = blockIdx.z;
    const __half* A = Ab + (long)bz * sA;
    const __half* B = Bb + (long)bz * sB;
    OutT* C = Cb + (long)bz * sC;
    const int m0 = blockIdx.y * BM;
    const int n0 = blockIdx.x * BN;

    const int wid = tid >> 5, lane = tid & 31;
    const int wm = (wid & 1) * 64;
    const int wn = (wid >> 1) * 64;

    float acc[4][8][4] = {};

    // ---- staging: A 1024 chunks (4/thread), B 2048 chunks (8/thread) ----
    auto stage = [&](int k0, int buf) {
        const uint32_t ab = smb + buf * STG_BYTES;
        const uint32_t bb = ab + ASZ;
        #pragma unroll
        for (int i = 0; i < 4; i++) {
            const int c = tid + i * 256;
            if (!TA) {
                const int row = c >> 3, ch = c & 7;
                const int sw = ch ^ (row & 7);
                cp16(ab + row * 128 + sw * 16,
                     &A[(long)(m0 + row) * lda + k0 + ch * 8]);
            } else {
                const int row = c >> 4, ch = c & 15;
                const int sw = (ch & 8) | ((ch ^ row) & 7);
                cp16(ab + row * 256 + sw * 16,
                     &A[(long)(k0 + row) * lda + m0 + ch * 8]);
            }
        }
        #pragma unroll
        for (int i = 0; i < 8; i++) {
            const int c = tid + i * 256;
            if (!TB) {
                const int row = c >> 5, ch = c & 31;
                const int sw = (ch & 24) | ((ch ^ row) & 7);
                cp16(bb + row * 512 + sw * 16,
                     &B[(long)(k0 + row) * ldb + n0 + ch * 8]);
            } else {
                const int row = c >> 3, ch = c & 7;
                const int sw = ch ^ (row & 7);
                cp16(bb + row * 128 + sw * 16,
                     &B[(long)(n0 + row) * ldb + k0 + ch * 8]);
            }
        }
        cp_commit();
    };

    stage(0, 0);
    stage(BK, 1);

    const int T = K / BK;
    for (int t = 0; t < T; t++) {
        cp_wait1();
        __syncthreads();
        if (t + 2 < T) stage((t + 2) * BK, (t + 2) % NSTAGE);

        const uint32_t ab = smb + (t % NSTAGE) * STG_BYTES;
        const uint32_t bb = ab + ASZ;

        #pragma unroll
        for (int ks = 0; ks < BK; ks += 16) {
            uint32_t a[4][4], b[8][2];
            // ---- A fragments: 4x ldsm4 ----
            #pragma unroll
            for (int mt = 0; mt < 4; mt++) {
                if (!TA) {
                    const int row = wm + mt * 16 + (lane & 15);
                    const int ch = (ks >> 3) + (lane >> 4);
                    const int sw = ch ^ (row & 7);
                    ldsm4(a[mt], ab + row * 128 + sw * 16);
                } else {
                    const int kk = ks + (lane >> 4) * 8 + (lane & 7);
                    const int mm = wm + mt * 16 + ((lane >> 3) & 1) * 8;
                    const int ch = mm >> 3;
                    const int sw = (ch & 8) | ((ch ^ kk) & 7);
                    ldsm4t(a[mt], ab + kk * 256 + sw * 16);
                }
            }
            // ---- B fragments: 4x ldsm4 (16 cols each) ----
            #pragma unroll
            for (int nt2 = 0; nt2 < 4; nt2++) {
                uint32_t r[4];
                if (!TB) {
                    const int kk = ks + ((lane >> 3) & 1) * 8 + (lane & 7);
                    const int ncol = wn + nt2 * 16 + ((lane >> 4) & 1) * 8;
                    const int ch = ncol >> 3;
                    const int sw = (ch & 24) | ((ch ^ kk) & 7);
                    ldsm4t(r, bb + kk * 512 + sw * 16);
                } else {
                    const int nn = wn + nt2 * 16 + ((lane >> 4) & 1) * 8 + (lane & 7);
                    const int ch = (ks >> 3) + ((lane >> 3) & 1);
                    const int sw = ch ^ (nn & 7);
                    ldsm4(r, bb + nn * 128 + sw * 16);
                }
                b[2*nt2][0] = r[0]; b[2*nt2][1] = r[1];
                b[2*nt2+1][0] = r[2]; b[2*nt2+1][1] = r[3];
            }
            #pragma unroll
            for (int mt = 0; mt < 4; mt++)
                #pragma unroll
                for (int nt = 0; nt < 8; nt++)
                    mma16816(acc[mt][nt], a[mt], b[nt]);
        }
    }
    cp_wait0();

    // ---- epilogue ----
    const int r0 = m0 + wm + (lane >> 2);
    const int c0 = n0 + wn + (lane & 3) * 2;
    #pragma unroll
    for (int mt = 0; mt < 4; mt++) {
        #pragma unroll
        for (int nt = 0; nt < 8; nt++) {
            const float* a4 = acc[mt][nt];
            const int r = r0 + mt * 16;
            const int c = c0 + nt * 8;
            #pragma unroll
            for (int h = 0; h < 2; h++) {
                const int rr = r + h * 8;
                const float bi = bias ? bias[rr] : 0.f;
                float vx = fmaf(a4[h * 2 + 0], alpha, bi);
                float vy = fmaf(a4[h * 2 + 1], alpha, bi);
                const long off = (long)rr * ldc + c;
                if (resid) {
                    const float2 rv = *reinterpret_cast<const float2*>(&resid[(long)bz * sR + off]);
                    vx += rv.x; vy += rv.y;
                }
                store2(&C[off], vx, vy);
            }
        }
    }
}

// ---------------------------------------------------------------------------
extern "C" void kernel_launch(void* const* d_in, const int* in_sizes, int n_in,
                              void* d_out, int out_size)
{
    const float* x     = (const float*)d_in[0];
    const float* gamma = (const float*)d_in[1];
    const float* beta  = (const float*)d_in[2];
    const float* wq    = (const float*)d_in[3];
    const float* bq    = (const float*)d_in[4];
    const float* wk    = (const float*)d_in[5];
    const float* bk    = (const float*)d_in[6];
    const float* wv    = (const float*)d_in[7];
    const float* bv    = (const float*)d_in[8];
    const float* wp    = (const float*)d_in[9];
    const float* bp    = (const float*)d_in[10];
    float* out = (float*)d_out;

    __half *hn, *q, *k, *v, *s, *w;
    cudaGetSymbolAddress((void**)&hn, g_hn);
    cudaGetSymbolAddress((void**)&q,  g_q);
    cudaGetSymbolAddress((void**)&k,  g_k);
    cudaGetSymbolAddress((void**)&v,  g_v);
    cudaGetSymbolAddress((void**)&s,  g_s);
    cudaGetSymbolAddress((void**)&w,  g_w);

    const long HH = (long)H_ * H_;
    const long CC = (long)C_ * C_;
    const float scale = 0.044194173824159216f;   // 1/sqrt(512)

    cudaFuncSetAttribute(hgemm_kernel<false, false, __half>, cudaFuncAttributeMaxDynamicSharedMemorySize, GEMM_SMEM);
    cudaFuncSetAttribute(hgemm_kernel<false, false, float >, cudaFuncAttributeMaxDynamicSharedMemorySize, GEMM_SMEM);
    cudaFuncSetAttribute(hgemm_kernel<true,  false, __half>, cudaFuncAttributeMaxDynamicSharedMemorySize, GEMM_SMEM);
    cudaFuncSetAttribute(hgemm_kernel<false, true,  __half>, cudaFuncAttributeMaxDynamicSharedMemorySize, GEMM_SMEM);

    // 0. weights -> fp16 ; 1. GroupNorm -> fp16
    w2h_kernel<<<1024, 256>>>(wq, wk, wv, wp, w);
    gn_kernel<<<B_ * G_, 256>>>(x, gamma, beta, hn);

    // 2-4. q/k/v = W @ hn_b + bias   (A=[m,k], B=[k,n])
    dim3 gqkv(H_ / BN, C_ / BM, B_);
    hgemm_kernel<false, false, __half><<<gqkv, 256, GEMM_SMEM>>>(w + 0*CC, hn, q, C_, C_, H_, H_,
                                                                 0, CH, CH, bq, 1.f, nullptr, 0);
    hgemm_kernel<false, false, __half><<<gqkv, 256, GEMM_SMEM>>>(w + 1*CC, hn, k, C_, C_, H_, H_,
                                                                 0, CH, CH, bk, 1.f, nullptr, 0);
    hgemm_kernel<false, false, __half><<<gqkv, 256, GEMM_SMEM>>>(w + 2*CC, hn, v, C_, C_, H_, H_,
                                                                 0, CH, CH, bv, 1.f, nullptr, 0);

    // 5. scores s[b,i,j] = scale * sum_c q[b,c,i] k[b,c,j]   (A=[k,m], B=[k,n])
    dim3 gsc(H_ / BN, H_ / BM, B_);
    hgemm_kernel<true, false, __half><<<gsc, 256, GEMM_SMEM>>>(q, k, s, C_, H_, H_, H_,
                                                               CH, CH, HH, nullptr, scale, nullptr, 0);

    // 6. softmax over j
    softmax_kernel<<<B_ * H_, 256>>>(s);

    // 7. h_[b,c,i] = sum_j v[b,c,j] p[i,j]   (A=[m,k], B=[n,k]) -> reuse g_hn
    dim3 gav(H_ / BN, C_ / BM, B_);
    hgemm_kernel<false, true, __half><<<gav, 256, GEMM_SMEM>>>(v, s, hn, H_, H_, H_, H_,
                                                               CH, HH, CH, nullptr, 1.f, nullptr, 0);

    // 8. out = x + Wp @ h_ + bp  (fp32 out, residual)
    hgemm_kernel<false, false, float><<<gqkv, 256, GEMM_SMEM>>>(w + 3*CC, hn, out, C_, C_, H_, H_,
                                                                0, CH, CH, bp, 1.f, x, CH);
}

// round 9
// speedup vs baseline: 7.8540x; 1.0934x over previous
#include <cuda_runtime.h>
#include <cuda_fp16.h>
#include <math.h>
#include <stdint.h>

#define B_ 8
#define C_ 512
#define H_ 2048
#define G_ 32
#define CPG 16
static const long CH = (long)C_ * H_;

// Scratch (device globals: allocation-free contract). All fp16 intermediates.
__device__ __half g_hn[B_*C_*H_];        // GN output; later reused for attn*V output
__device__ __half g_q [B_*C_*H_];
__device__ __half g_k [B_*C_*H_];
__device__ __half g_v [B_*C_*H_];
__device__ __half g_s [(long)B_*H_*H_]; // attention exp-scores (64 MB fp16)
__device__ __half g_w [4*C_*C_];        // fp16 weights: wq,wk,wv,wp
__device__ float  g_rsum[B_*H_];        // softmax row sums (of exp(x-8))

__device__ __forceinline__ uint32_t smem_u32(const void* p) {
    return (uint32_t)__cvta_generic_to_shared(p);
}
__device__ __forceinline__ void st_h4(__half* dst, float4 v) {
    __half2 lo = __floats2half2_rn(v.x, v.y);
    __half2 hi = __floats2half2_rn(v.z, v.w);
    uint2 u;
    u.x = *reinterpret_cast<uint32_t*>(&lo);
    u.y = *reinterpret_cast<uint32_t*>(&hi);
    *reinterpret_cast<uint2*>(dst) = u;
}

// ---------------------------------------------------------------------------
// Weight fp32 -> fp16 conversion (4 x 512 x 512) + zero rsum
// ---------------------------------------------------------------------------
__global__ __launch_bounds__(256) void w2h_kernel(const float* __restrict__ wq,
                                                  const float* __restrict__ wk,
                                                  const float* __restrict__ wv,
                                                  const float* __restrict__ wp,
                                                  __half* __restrict__ dst)
{
    const int gid = blockIdx.x * 256 + threadIdx.x;
    if (gid < B_ * H_) g_rsum[gid] = 0.f;
    const int mat = gid >> 16;
    const int off = (gid & 65535) * 4;
    const float* src = (mat == 0) ? wq : (mat == 1) ? wk : (mat == 2) ? wv : wp;
    float4 v = *reinterpret_cast<const float4*>(src + off);
    st_h4(&dst[(long)mat * C_ * C_ + off], v);
}

// ---------------------------------------------------------------------------
// GroupNorm -> fp16 output
// ---------------------------------------------------------------------------
__global__ __launch_bounds__(256) void gn_kernel(const float* __restrict__ x,
                                                 const float* __restrict__ gamma,
                                                 const float* __restrict__ beta,
                                                 __half* __restrict__ hn)
{
    const int b = blockIdx.x >> 5;
    const int g = blockIdx.x & 31;
    const long base = ((long)b * C_ + (long)g * CPG) * H_;
    const float4* xp = reinterpret_cast<const float4*>(x + base);
    const int NE4 = CPG * H_ / 4;
    const int tid = threadIdx.x;

    float s = 0.f, ss = 0.f;
    for (int i = tid; i < NE4; i += 256) {
        float4 v = xp[i];
        s  += v.x + v.y + v.z + v.w;
        ss += v.x*v.x + v.y*v.y + v.z*v.z + v.w*v.w;
    }
    __shared__ float rs[8], rss[8];
    #pragma unroll
    for (int o = 16; o > 0; o >>= 1) {
        s  += __shfl_down_sync(0xFFFFFFFFu, s,  o);
        ss += __shfl_down_sync(0xFFFFFFFFu, ss, o);
    }
    if ((tid & 31) == 0) { rs[tid >> 5] = s; rss[tid >> 5] = ss; }
    __syncthreads();
    if (tid < 32) {
        s  = (tid < 8) ? rs[tid]  : 0.f;
        ss = (tid < 8) ? rss[tid] : 0.f;
        #pragma unroll
        for (int o = 4; o > 0; o >>= 1) {
            s  += __shfl_down_sync(0xFFFFFFFFu, s,  o);
            ss += __shfl_down_sync(0xFFFFFFFFu, ss, o);
        }
        if (tid == 0) { rs[0] = s; rss[0] = ss; }
    }
    __syncthreads();
    const float mean = rs[0] * (1.f / (CPG * H_));
    const float var  = rss[0] * (1.f / (CPG * H_)) - mean * mean;
    const float inv  = rsqrtf(var + 1e-6f);

    for (int i = tid; i < NE4; i += 256) {
        const int c = g * CPG + (i * 4) / H_;
        const float gm = gamma[c] * inv;
        const float bt = beta[c] - mean * gm;
        float4 v = xp[i];
        float4 o;
        o.x = v.x * gm + bt; o.y = v.y * gm + bt;
        o.z = v.z * gm + bt; o.w = v.w * gm + bt;
        st_h4(&hn[base + (long)i * 4], o);
    }
}

// ---------------------------------------------------------------------------
// Tensor-core fp16 GEMM, XOR-swizzled smem, BK=64, 3 stages,
// ks-level fragment double-buffering.
//   C[m,n] = alpha * sum_k A(m,k)*B(k,n) (+bias[m]) (+resid fp32)
//   EXPSUM: out = exp(alpha*acc - 8), atomic row-sum into rsum[bz*H+m]
//   RSCALE: out *= 1/rsum[bz*H + n]
// ---------------------------------------------------------------------------
#define BM 128
#define BN 128
#define BK 64
#define NSTAGE 3
#define STG_BYTES 32768
#define GEMM_SMEM (NSTAGE * STG_BYTES)

__device__ __forceinline__ void cp16(uint32_t s, const void* g) {
    asm volatile("cp.async.cg.shared.global [%0], [%1], 16;" :: "r"(s), "l"(g));
}
__device__ __forceinline__ void cp_commit() { asm volatile("cp.async.commit_group;"); }
__device__ __forceinline__ void cp_wait1() { asm volatile("cp.async.wait_group 1;"); }
__device__ __forceinline__ void cp_wait0() { asm volatile("cp.async.wait_group 0;"); }

__device__ __forceinline__ void ldsm4(uint32_t* r, uint32_t a) {
    asm volatile("ldmatrix.sync.aligned.m8n8.x4.shared.b16 {%0,%1,%2,%3}, [%4];"
                 : "=r"(r[0]), "=r"(r[1]), "=r"(r[2]), "=r"(r[3]) : "r"(a));
}
__device__ __forceinline__ void ldsm4t(uint32_t* r, uint32_t a) {
    asm volatile("ldmatrix.sync.aligned.m8n8.x4.trans.shared.b16 {%0,%1,%2,%3}, [%4];"
                 : "=r"(r[0]), "=r"(r[1]), "=r"(r[2]), "=r"(r[3]) : "r"(a));
}
__device__ __forceinline__ void mma16816(float* c, const uint32_t* a, const uint32_t* b) {
    asm volatile("mma.sync.aligned.m16n8k16.row.col.f32.f16.f16.f32 "
                 "{%0,%1,%2,%3}, {%4,%5,%6,%7}, {%8,%9}, {%0,%1,%2,%3};"
                 : "+f"(c[0]), "+f"(c[1]), "+f"(c[2]), "+f"(c[3])
                 : "r"(a[0]), "r"(a[1]), "r"(a[2]), "r"(a[3]), "r"(b[0]), "r"(b[1]));
}
__device__ __forceinline__ void store2(float* p, float x, float y) {
    *reinterpret_cast<float2*>(p) = make_float2(x, y);
}
__device__ __forceinline__ void store2(__half* p, float x, float y) {
    *reinterpret_cast<__half2*>(p) = __floats2half2_rn(x, y);
}

template<bool TA, bool TB, typename OutT, bool EXPSUM, bool RSCALE>
__global__ __launch_bounds__(256) void hgemm_kernel(
    const __half* __restrict__ Ab, const __half* __restrict__ Bb, OutT* __restrict__ Cb,
    int K, int lda, int ldb, int ldc,
    long sA, long sB, long sC,
    const float* __restrict__ bias, float alpha,
    const float* __restrict__ resid, long sR,
    float* __restrict__ rsum)
{
    extern __shared__ __align__(128) char sm[];
    const uint32_t smb = smem_u32(sm);

    const int tid = threadIdx.x;
    const int bz = blockIdx.z;
    const __half* A = Ab + (long)bz * sA;
    const __half* B = Bb + (long)bz * sB;
    OutT* C = Cb + (long)bz * sC;
    const int m0 = blockIdx.y * BM;
    const int n0 = blockIdx.x * BN;

    const int wid = tid >> 5, lane = tid & 31;
    const int wm = (wid & 1) * 64;
    const int wn = (wid >> 1) * 32;

    float acc[4][4][4] = {};

    auto stage = [&](int k0, int buf) {
        const uint32_t ab = smb + buf * STG_BYTES;
        const uint32_t bb = ab + 16384;
        #pragma unroll
        for (int i = 0; i < 4; i++) {
            const int c = tid + i * 256;
            if (!TA) {
                const int row = c >> 3, ch = c & 7;
                const int sw = ch ^ (row & 7);
                cp16(ab + row * 128 + sw * 16,
                     &A[(long)(m0 + row) * lda + k0 + ch * 8]);
            } else {
                const int row = c >> 4, ch = c & 15;
                const int sw = (ch & 8) | ((ch ^ row) & 7);
                cp16(ab + row * 256 + sw * 16,
                     &A[(long)(k0 + row) * lda + m0 + ch * 8]);
            }
        }
        #pragma unroll
        for (int i = 0; i < 4; i++) {
            const int c = tid + i * 256;
            if (!TB) {
                const int row = c >> 4, ch = c & 15;
                const int sw = (ch & 8) | ((ch ^ row) & 7);
                cp16(bb + row * 256 + sw * 16,
                     &B[(long)(k0 + row) * ldb + n0 + ch * 8]);
            } else {
                const int row = c >> 3, ch = c & 7;
                const int sw = ch ^ (row & 7);
                cp16(bb + row * 128 + sw * 16,
                     &B[(long)(n0 + row) * ldb + k0 + ch * 8]);
            }
        }
        cp_commit();
    };

    // fragment loader for one ks step (16 wide)
    auto load_frags = [&](int ks, uint32_t a[4][4], uint32_t b[4][2],
                          uint32_t ab, uint32_t bb) {
        #pragma unroll
        for (int mt = 0; mt < 4; mt++) {
            if (!TA) {
                const int row = wm + mt * 16 + (lane & 15);
                const int ch = (ks >> 3) + (lane >> 4);
                const int sw = ch ^ (row & 7);
                ldsm4(a[mt], ab + row * 128 + sw * 16);
            } else {
                const int kk = ks + (lane >> 4) * 8 + (lane & 7);
                const int mm = wm + mt * 16 + ((lane >> 3) & 1) * 8;
                const int ch = mm >> 3;
                const int sw = (ch & 8) | ((ch ^ kk) & 7);
                ldsm4t(a[mt], ab + kk * 256 + sw * 16);
            }
        }
        #pragma unroll
        for (int nt2 = 0; nt2 < 2; nt2++) {
            uint32_t r[4];
            if (!TB) {
                const int kk = ks + ((lane >> 3) & 1) * 8 + (lane & 7);
                const int ncol = wn + nt2 * 16 + ((lane >> 4) & 1) * 8;
                const int ch = ncol >> 3;
                const int sw = (ch & 8) | ((ch ^ kk) & 7);
                ldsm4t(r, bb + kk * 256 + sw * 16);
            } else {
                const int nn = wn + nt2 * 16 + ((lane >> 4) & 1) * 8 + (lane & 7);
                const int ch = (ks >> 3) + ((lane >> 3) & 1);
                const int sw = ch ^ (nn & 7);
                ldsm4(r, bb + nn * 128 + sw * 16);
            }
            b[2*nt2][0] = r[0]; b[2*nt2][1] = r[1];
            b[2*nt2+1][0] = r[2]; b[2*nt2+1][1] = r[3];
        }
    };

    stage(0, 0);
    stage(BK, 1);

    const int T = K / BK;
    for (int t = 0; t < T; t++) {
        cp_wait1();
        __syncthreads();
        if (t + 2 < T) stage((t + 2) * BK, (t + 2) % NSTAGE);

        const uint32_t ab = smb + (t % NSTAGE) * STG_BYTES;
        const uint32_t bb = ab + 16384;

        uint32_t fa[2][4][4], fb[2][4][2];
        load_frags(0, fa[0], fb[0], ab, bb);
        #pragma unroll
        for (int s4 = 0; s4 < 4; s4++) {
            const int cur = s4 & 1, nxt = cur ^ 1;
            if (s4 < 3) load_frags((s4 + 1) * 16, fa[nxt], fb[nxt], ab, bb);
            #pragma unroll
            for (int mt = 0; mt < 4; mt++)
                #pragma unroll
                for (int nt = 0; nt < 4; nt++)
                    mma16816(acc[mt][nt], fa[cur][mt], fb[cur][nt]);
        }
    }
    cp_wait0();

    // ---- epilogue ----
    const int r0 = m0 + wm + (lane >> 2);
    const int c0 = n0 + wn + (lane & 3) * 2;
    if (EXPSUM) {
        #pragma unroll
        for (int mt = 0; mt < 4; mt++) {
            #pragma unroll
            for (int h = 0; h < 2; h++) {
                const int rr = r0 + mt * 16 + h * 8;
                float rsl = 0.f;
                #pragma unroll
                for (int nt = 0; nt < 4; nt++) {
                    const float* a4 = acc[mt][nt];
                    float vx = expf(fmaf(a4[h*2+0], alpha, -8.f));
                    float vy = expf(fmaf(a4[h*2+1], alpha, -8.f));
                    store2(&C[(long)rr * ldc + c0 + nt * 8], vx, vy);
                    rsl += vx + vy;
                }
                rsl += __shfl_xor_sync(0xFFFFFFFFu, rsl, 1);
                rsl += __shfl_xor_sync(0xFFFFFFFFu, rsl, 2);
                if ((lane & 3) == 0)
                    atomicAdd(&rsum[(long)bz * H_ + rr], rsl);
            }
        }
    } else {
        #pragma unroll
        for (int mt = 0; mt < 4; mt++) {
            #pragma unroll
            for (int nt = 0; nt < 4; nt++) {
                const float* a4 = acc[mt][nt];
                const int c = c0 + nt * 8;
                float sx = 1.f, sy = 1.f;
                if (RSCALE) {
                    sx = 1.f / rsum[(long)bz * H_ + c];
                    sy = 1.f / rsum[(long)bz * H_ + c + 1];
                }
                #pragma unroll
                for (int h = 0; h < 2; h++) {
                    const int rr = r0 + mt * 16 + h * 8;
                    const float bi = bias ? bias[rr] : 0.f;
                    float vx = fmaf(a4[h * 2 + 0], alpha, bi) * sx;
                    float vy = fmaf(a4[h * 2 + 1], alpha, bi) * sy;
                    const long off = (long)rr * ldc + c;
                    if (resid) {
                        const float2 rv = *reinterpret_cast<const float2*>(&resid[(long)bz * sR + off]);
                        vx += rv.x; vy += rv.y;
                    }
                    store2(&C[off], vx, vy);
                }
            }
        }
    }
}

// ---------------------------------------------------------------------------
extern "C" void kernel_launch(void* const* d_in, const int* in_sizes, int n_in,
                              void* d_out, int out_size)
{
    const float* x     = (const float*)d_in[0];
    const float* gamma = (const float*)d_in[1];
    const float* beta  = (const float*)d_in[2];
    const float* wq    = (const float*)d_in[3];
    const float* bq    = (const float*)d_in[4];
    const float* wk    = (const float*)d_in[5];
    const float* bk    = (const float*)d_in[6];
    const float* wv    = (const float*)d_in[7];
    const float* bv    = (const float*)d_in[8];
    const float* wp    = (const float*)d_in[9];
    const float* bp    = (const float*)d_in[10];
    float* out = (float*)d_out;

    __half *hn, *q, *k, *v, *s, *w;
    float* rsum;
    cudaGetSymbolAddress((void**)&hn, g_hn);
    cudaGetSymbolAddress((void**)&q,  g_q);
    cudaGetSymbolAddress((void**)&k,  g_k);
    cudaGetSymbolAddress((void**)&v,  g_v);
    cudaGetSymbolAddress((void**)&s,  g_s);
    cudaGetSymbolAddress((void**)&w,  g_w);
    cudaGetSymbolAddress((void**)&rsum, g_rsum);

    const long HH = (long)H_ * H_;
    const long CC = (long)C_ * C_;
    const float scale = 0.044194173824159216f;   // 1/sqrt(512)

    cudaFuncSetAttribute((const void*)hgemm_kernel<false, false, __half, false, false>, cudaFuncAttributeMaxDynamicSharedMemorySize, GEMM_SMEM);
    cudaFuncSetAttribute((const void*)hgemm_kernel<false, false, float,  false, false>, cudaFuncAttributeMaxDynamicSharedMemorySize, GEMM_SMEM);
    cudaFuncSetAttribute((const void*)hgemm_kernel<true,  false, __half, true,  false>, cudaFuncAttributeMaxDynamicSharedMemorySize, GEMM_SMEM);
    cudaFuncSetAttribute((const void*)hgemm_kernel<false, true,  __half, false, true >, cudaFuncAttributeMaxDynamicSharedMemorySize, GEMM_SMEM);

    // 0. weights -> fp16 (+ zero rsum) ; 1. GroupNorm -> fp16
    w2h_kernel<<<1024, 256>>>(wq, wk, wv, wp, w);
    gn_kernel<<<B_ * G_, 256>>>(x, gamma, beta, hn);

    // 2-4. q/k/v = W @ hn_b + bias   (A=[m,k], B=[k,n])
    dim3 gqkv(H_ / BN, C_ / BM, B_);
    hgemm_kernel<false, false, __half, false, false><<<gqkv, 256, GEMM_SMEM>>>(
        w + 0*CC, hn, q, C_, C_, H_, H_, 0, CH, CH, bq, 1.f, nullptr, 0, nullptr);
    hgemm_kernel<false, false, __half, false, false><<<gqkv, 256, GEMM_SMEM>>>(
        w + 1*CC, hn, k, C_, C_, H_, H_, 0, CH, CH, bk, 1.f, nullptr, 0, nullptr);
    hgemm_kernel<false, false, __half, false, false><<<gqkv, 256, GEMM_SMEM>>>(
        w + 2*CC, hn, v, C_, C_, H_, H_, 0, CH, CH, bv, 1.f, nullptr, 0, nullptr);

    // 5. P[b,i,j] = exp(scale * sum_c q[b,c,i] k[b,c,j] - 8), rowsum -> rsum
    dim3 gsc(H_ / BN, H_ / BM, B_);
    hgemm_kernel<true, false, __half, true, false><<<gsc, 256, GEMM_SMEM>>>(
        q, k, s, C_, H_, H_, H_, CH, CH, HH, nullptr, scale, nullptr, 0, rsum);

    // 6. h_[b,c,i] = (1/rsum[i]) * sum_j v[b,c,j] P[i,j]   (A=[m,k], B=[n,k])
    dim3 gav(H_ / BN, C_ / BM, B_);
    hgemm_kernel<false, true, __half, false, true><<<gav, 256, GEMM_SMEM>>>(
        v, s, hn, H_, H_, H_, H_, CH, HH, CH, nullptr, 1.f, nullptr, 0, rsum);

    // 7. out = x + Wp @ h_ + bp  (fp32 out, residual)
    hgemm_kernel<false, false, float, false, false><<<gqkv, 256, GEMM_SMEM>>>(
        w + 3*CC, hn, out, C_, C_, H_, H_, 0, CH, CH, bp, 1.f, x, CH, nullptr);
}